// round 10
// baseline (speedup 1.0000x reference)
#include <cuda_runtime.h>

// ---------------- scratch ----------------
__device__ __align__(16) float d_Y0[16 * 16 * 258 * 258];   // (B,16,258,258)
__device__ __align__(16) float d_Y1[16 * 32 * 130 * 130];   // (B,32,130,130)
__device__ float d_blk0[1024];   // [r2][c2][m16][n16]
__device__ float d_blk1[512];    // [g2][m16][n16]
__device__ float d_part[192];
__device__ float d_bscale[2];

typedef unsigned long long u64;

__device__ __forceinline__ u64 pk2(float a, float b) {
    u64 r;
    asm("mov.b64 %0, {%1, %2};" : "=l"(r) : "r"(__float_as_uint(a)), "r"(__float_as_uint(b)));
    return r;
}
__device__ __forceinline__ u64 dup2(float a) { return pk2(a, a); }
__device__ __forceinline__ void dfma(u64& d, u64 a, u64 b) {
    asm("fma.rn.f32x2 %0, %1, %2, %0;" : "+l"(d) : "l"(a), "l"(b));
}
__device__ __forceinline__ float2 up2(u64 v) {
    unsigned lo, hi;
    asm("mov.b64 {%0, %1}, %2;" : "=r"(lo), "=r"(hi) : "l"(v));
    return make_float2(__uint_as_float(lo), __uint_as_float(hi));
}
__device__ __forceinline__ void ldw4(const u64* p, u64 wr[4]) {
    const ulonglong2* q = (const ulonglong2*)p;
    ulonglong2 a = q[0], b = q[1];
    wr[0] = a.x; wr[1] = a.y; wr[2] = b.x; wr[3] = b.y;
}

// ---------------- P1: partial sum of squares ----------------
__global__ __launch_bounds__(256) void k_ssq(const float* __restrict__ b0,
                                             const float* __restrict__ b1) {
    __shared__ float red[256];
    int bid = blockIdx.x, t = threadIdx.x;
    const float* src; long base;
    if (bid < 128) { src = b0; base = (long)bid * 8192; }
    else           { src = b1; base = (long)(bid - 128) * 8192; }
    float s = 0.f;
#pragma unroll
    for (int k = 0; k < 32; k++) { float v = __ldg(src + base + k * 256 + t); s += v * v; }
    red[t] = s; __syncthreads();
    for (int off = 128; off; off >>= 1) { if (t < off) red[t] += red[t + off]; __syncthreads(); }
    if (t == 0) d_part[bid] = red[0];
}

// ---------------- P2 (parallel): bscale + Gram matrices ----------------
__global__ __launch_bounds__(256) void k_prep(const float* __restrict__ W00,
                                              const float* __restrict__ W10,
                                              const float* __restrict__ W11,
                                              const float* __restrict__ g) {
    __shared__ float sw[9216];
    int blk = blockIdx.x, t = threadIdx.x;
    if (blk == 0 && t == 0) {
        float s0 = 0.f, s1 = 0.f;
        for (int i = 0; i < 128; i++) s0 += d_part[i];
        for (int i = 128; i < 192; i++) s1 += d_part[i];
        d_bscale[0] = __ldg(g) * rsqrtf(s0);
        d_bscale[1] = __ldg(g + 1) * rsqrtf(s1);
    }
    if (blk < 4) {
        // blk0 entries [blk*256, blk*256+256)
        for (int i = t; i < 2304; i += 256) sw[i] = __ldg(W00 + i);
        for (int i = t; i < 4608; i += 256) sw[2304 + i] = __ldg(W10 + i);
        __syncthreads();
        const float* s0 = sw;
        const float* s1 = sw + 2304;
        int e = blk * 256 + t;
        int n = e & 15, m = (e >> 4) & 15, c = (e >> 8) & 1, r = (e >> 9) & 1;
        float acc = 0.f;
        for (int o = 0; o < 16; o++) {
            const float* pm = s0 + (o * 16 + m) * 9;
            const float* pn = s0 + (o * 16 + n) * 9;
#pragma unroll
            for (int ij = 0; ij < 9; ij++) acc += pm[ij] * pn[ij];
        }
#pragma unroll
        for (int i1 = 0; i1 < 3; i1++) {
            if (((i1 + 1) & 1) != r) continue;
#pragma unroll
            for (int j1 = 0; j1 < 3; j1++) {
                if (((j1 + 1) & 1) != c) continue;
                int ij = i1 * 3 + j1;
                for (int o = 0; o < 32; o++)
                    acc += s1[(o * 16 + m) * 9 + ij] * s1[(o * 16 + n) * 9 + ij];
            }
        }
        d_blk0[e] = acc;
    } else {
        // blk1 entries [(blk-4)*256, ...)
        for (int i = t; i < 9216; i += 256) sw[i] = __ldg(W11 + i);
        __syncthreads();
        int e = (blk - 4) * 256 + t;   // [0,512)
        int n = e & 15, m = (e >> 4) & 15, gg = e >> 8;
        float acc = 0.f;
        for (int o = 0; o < 32; o++) {
            const float* pm = sw + (o * 32 + gg * 16 + m) * 9;
            const float* pn = sw + (o * 32 + gg * 16 + n) * 9;
#pragma unroll
            for (int ij = 0; ij < 9; ij++) acc += pm[ij] * pn[ij];
        }
        d_blk1[e] = acc;
    }
}

// ------- Y0 = conv(x0, W00, s1, p2) -> (B,16,258,258); 8 oc per block ---------
__global__ __launch_bounds__(256, 3) void k_y0(const float* __restrict__ x0,
                                               const float* __restrict__ W00) {
    extern __shared__ u64 sm[];   // 576: [(ic*9+tap)*4+ip]
    int t = threadIdx.x;
    int half = blockIdx.z & 1, b = blockIdx.z >> 1;
    int ocb = half * 8;
    for (int idx = t; idx < 576; idx += 256) {
        int ip = idx & 3, rest = idx >> 2, tap = rest % 9, ic = rest / 9;
        float wa = __ldg(W00 + ((ocb + 2 * ip) * 16 + ic) * 9 + tap);
        float wb = __ldg(W00 + ((ocb + 2 * ip + 1) * 16 + ic) * 9 + tap);
        sm[idx] = pk2(wa, wb);
    }
    __syncthreads();
    int item = blockIdx.x * 256 + t;
    int r = item / 65, q = item - r * 65;
    int w0 = q * 4;
    bool valid = (r < 258);
    u64 acc[4][4];
#pragma unroll
    for (int p = 0; p < 4; p++)
#pragma unroll
        for (int ip = 0; ip < 4; ip++) acc[p][ip] = 0ull;
    const float* xb = x0 + (long)b * 1048576;
#pragma unroll 1
    for (int ic = 0; ic < 16; ic++) {
        const float* xc = xb + ic * 65536;
        const u64* wbase = sm + ic * 36;
#pragma unroll
        for (int dy = 0; dy < 3; dy++) {
            int iy = r - 2 + dy;
            bool rowok = valid && iy >= 0 && iy < 256;
            float v[6];
#pragma unroll
            for (int j = 0; j < 6; j++) {
                int ix = w0 - 2 + j;
                v[j] = (rowok && ix >= 0 && ix < 256) ? __ldg(xc + iy * 256 + ix) : 0.f;
            }
#pragma unroll
            for (int dx = 0; dx < 3; dx++) {
                u64 wr[4];
                ldw4(wbase + (dy * 3 + dx) * 4, wr);
#pragma unroll
                for (int p = 0; p < 4; p++) {
                    u64 a = dup2(v[p + dx]);
#pragma unroll
                    for (int ip = 0; ip < 4; ip++) dfma(acc[p][ip], wr[ip], a);
                }
            }
        }
    }
    if (valid) {
        float* yb = d_Y0 + (long)b * 1065024 + (long)ocb * 66564 + r * 258 + w0;
#pragma unroll
        for (int p = 0; p < 4; p++) {
            if (w0 + p >= 258) break;
#pragma unroll
            for (int ip = 0; ip < 4; ip++) {
                float2 f = up2(acc[p][ip]);
                yb[(2 * ip) * 66564 + p] = f.x;
                yb[(2 * ip + 1) * 66564 + p] = f.y;
            }
        }
    }
}

// ------- Y1 = conv(x0,W10,s2,p3)+conv(x1,W11,s1,p2); 8 oc per block -----------
__global__ __launch_bounds__(256, 3) void k_y1(const float* __restrict__ x0,
                                               const float* __restrict__ x1,
                                               const float* __restrict__ W10,
                                               const float* __restrict__ W11) {
    extern __shared__ u64 sm[];   // sA 576 + sB 1152
    u64* sA = sm; u64* sB2 = sm + 576;
    int t = threadIdx.x;
    int qq = blockIdx.z & 3, b = blockIdx.z >> 2;
    int ocb = qq * 8;
    for (int idx = t; idx < 576; idx += 256) {
        int ip = idx & 3, rest = idx >> 2, tap = rest % 9, ic = rest / 9;
        float wa = __ldg(W10 + ((ocb + 2 * ip) * 16 + ic) * 9 + tap);
        float wb = __ldg(W10 + ((ocb + 2 * ip + 1) * 16 + ic) * 9 + tap);
        sA[idx] = pk2(wa, wb);
    }
    for (int idx = t; idx < 1152; idx += 256) {
        int ip = idx & 3, rest = idx >> 2, tap = rest % 9, ic = rest / 9;  // ic 0..31
        float wa = __ldg(W11 + ((ocb + 2 * ip) * 32 + ic) * 9 + tap);
        float wb = __ldg(W11 + ((ocb + 2 * ip + 1) * 32 + ic) * 9 + tap);
        sB2[idx] = pk2(wa, wb);
    }
    __syncthreads();
    int item = blockIdx.x * 256 + t;
    int u = item / 33, q = item - u * 33;
    int v0 = q * 4;
    bool valid = (u < 130);
    u64 acc[4][4];
#pragma unroll
    for (int p = 0; p < 4; p++)
#pragma unroll
        for (int ip = 0; ip < 4; ip++) acc[p][ip] = 0ull;
    const float* xa = x0 + (long)b * 1048576;
#pragma unroll 1
    for (int ic = 0; ic < 16; ic++) {
        const float* xc = xa + ic * 65536;
        const u64* wbase = sA + ic * 36;
#pragma unroll
        for (int dy = 0; dy < 3; dy++) {
            int iy = 2 * u - 3 + dy;
            bool rowok = valid && iy >= 0 && iy < 256;
            float v[9];
#pragma unroll
            for (int j = 0; j < 9; j++) {
                int ix = 2 * v0 - 3 + j;
                v[j] = (rowok && ix >= 0 && ix < 256) ? __ldg(xc + iy * 256 + ix) : 0.f;
            }
#pragma unroll
            for (int dx = 0; dx < 3; dx++) {
                u64 wr[4];
                ldw4(wbase + (dy * 3 + dx) * 4, wr);
#pragma unroll
                for (int p = 0; p < 4; p++) {
                    u64 a = dup2(v[2 * p + dx]);
#pragma unroll
                    for (int ip = 0; ip < 4; ip++) dfma(acc[p][ip], wr[ip], a);
                }
            }
        }
    }
    const float* xb1 = x1 + (long)b * 524288;
#pragma unroll 1
    for (int ic = 0; ic < 32; ic++) {
        const float* xc = xb1 + ic * 16384;
        const u64* wbase = sB2 + ic * 36;
#pragma unroll
        for (int dy = 0; dy < 3; dy++) {
            int iy = u - 2 + dy;
            bool rowok = valid && iy >= 0 && iy < 128;
            float v[6];
#pragma unroll
            for (int j = 0; j < 6; j++) {
                int ix = v0 - 2 + j;
                v[j] = (rowok && ix >= 0 && ix < 128) ? __ldg(xc + iy * 128 + ix) : 0.f;
            }
#pragma unroll
            for (int dx = 0; dx < 3; dx++) {
                u64 wr[4];
                ldw4(wbase + (dy * 3 + dx) * 4, wr);
#pragma unroll
                for (int p = 0; p < 4; p++) {
                    u64 a = dup2(v[p + dx]);
#pragma unroll
                    for (int ip = 0; ip < 4; ip++) dfma(acc[p][ip], wr[ip], a);
                }
            }
        }
    }
    if (valid) {
        float* yb = d_Y1 + (long)b * 540800 + (long)ocb * 16900 + u * 130 + v0;
#pragma unroll
        for (int p = 0; p < 4; p++) {
            if (v0 + p >= 130) break;
#pragma unroll
            for (int ip = 0; ip < 4; ip++) {
                float2 f = up2(acc[p][ip]);
                yb[(2 * ip) * 16900 + p] = f.x;
                yb[(2 * ip + 1) * 16900 + p] = f.y;
            }
        }
    }
}

// ---- Z0: out0 = -convt(Y0,W00) - convt(Y1,W10,s2) + diag + bias; 8 i/block ----
__global__ __launch_bounds__(256, 3) void k_z0(const float* __restrict__ x0,
                                               const float* __restrict__ W00,
                                               const float* __restrict__ W10,
                                               const float* __restrict__ b0,
                                               float* __restrict__ out) {
    extern __shared__ u64 sm[];   // sW 576 | sBk 256 | sT 1152
    u64* sW = sm; u64* sBk = sm + 576; u64* sT = sm + 832;
    int t = threadIdx.x;
    int ih = blockIdx.z & 1, b = blockIdx.z >> 1;
    int ib = ih * 8;
    for (int idx = t; idx < 576; idx += 256) {
        int ip = idx & 3, rest = idx >> 2, tap = rest % 9, o = rest / 9;
        float wa = -__ldg(W00 + (o * 16 + ib + 2 * ip) * 9 + tap);
        float wb = -__ldg(W00 + (o * 16 + ib + 2 * ip + 1) * 9 + tap);
        sW[idx] = pk2(wa, wb);
    }
    for (int idx = t; idx < 256; idx += 256) {
        int ip = idx & 3, n = (idx >> 2) & 15, rc = idx >> 6;
        float a0 = d_blk0[(rc * 16 + ib + 2 * ip) * 16 + n];
        float a1 = d_blk0[(rc * 16 + ib + 2 * ip + 1) * 16 + n];
        sBk[idx] = pk2(a0, a1);
    }
    for (int idx = t; idx < 1152; idx += 256) {
        int ip = idx & 3, rest = idx >> 2, o = rest & 31, tap = rest >> 5;
        float wa = -__ldg(W10 + (o * 16 + ib + 2 * ip) * 9 + tap);
        float wb = -__ldg(W10 + (o * 16 + ib + 2 * ip + 1) * 9 + tap);
        sT[idx] = pk2(wa, wb);
    }
    __syncthreads();
    int lane = t & 31, warp = t >> 5;
    int h = blockIdx.y * 8 + warp;
    int w0 = (blockIdx.x * 32 + lane) * 4;
    u64 acc[4][4];
#pragma unroll
    for (int p = 0; p < 4; p++)
#pragma unroll
        for (int ip = 0; ip < 4; ip++) acc[p][ip] = 0ull;

    // term1: -convt(Y0,W00)
    const float* yb = d_Y0 + (long)b * 1065024 + h * 258 + w0;
#pragma unroll 1
    for (int o = 0; o < 16; o++) {
        const float* yc = yb + o * 66564;
        float yv[3][6];
#pragma unroll
        for (int rr = 0; rr < 3; rr++) {
            float2 a = *reinterpret_cast<const float2*>(yc + rr * 258);
            float2 c = *reinterpret_cast<const float2*>(yc + rr * 258 + 2);
            float2 e = *reinterpret_cast<const float2*>(yc + rr * 258 + 4);
            yv[rr][0] = a.x; yv[rr][1] = a.y; yv[rr][2] = c.x;
            yv[rr][3] = c.y; yv[rr][4] = e.x; yv[rr][5] = e.y;
        }
        const u64* wbase = sW + o * 36;
#pragma unroll
        for (int dy = 0; dy < 3; dy++)
#pragma unroll
            for (int dx = 0; dx < 3; dx++) {
                u64 wr[4];
                ldw4(wbase + (dy * 3 + dx) * 4, wr);
#pragma unroll
                for (int p = 0; p < 4; p++) {
                    u64 a = dup2(yv[2 - dy][p + 2 - dx]);
#pragma unroll
                    for (int ip = 0; ip < 4; ip++) dfma(acc[p][ip], wr[ip], a);
                }
            }
    }
    // term2: -convt(Y1,W10,s2,p3,op1)
    {
        int qc = (w0 >> 1) + 1;
        int hp = h & 1;
        int ntap = hp ? 2 : 1;
        int dy0 = hp ? 0 : 1;
        int qr0 = hp ? ((h + 3) >> 1) : ((h >> 1) + 1);
        int qr1 = (h + 1) >> 1;
        const float* y1b = d_Y1 + (long)b * 540800;
#pragma unroll 1
        for (int o = 0; o < 32; o++) {
            const float* yo = y1b + o * 16900;
            for (int tt = 0; tt < ntap; tt++) {
                int dy = tt ? 2 : dy0;
                int qr = tt ? qr1 : qr0;
                const float* yr = yo + qr * 130 + qc;
                float yA = __ldg(yr), yB = __ldg(yr + 1), yC = __ldg(yr + 2);
                u64 aA = dup2(yA), aB = dup2(yB), aC = dup2(yC);
                u64 r0[4], r1[4], r2[4];
                ldw4(sT + ((dy * 3 + 0) * 32 + o) * 4, r0);
                ldw4(sT + ((dy * 3 + 1) * 32 + o) * 4, r1);
                ldw4(sT + ((dy * 3 + 2) * 32 + o) * 4, r2);
#pragma unroll
                for (int ip = 0; ip < 4; ip++) {
                    dfma(acc[0][ip], r1[ip], aA);
                    dfma(acc[1][ip], r0[ip], aB);
                    dfma(acc[1][ip], r2[ip], aA);
                    dfma(acc[2][ip], r1[ip], aB);
                    dfma(acc[3][ip], r0[ip], aC);
                    dfma(acc[3][ip], r2[ip], aB);
                }
            }
        }
    }
    // term3: +diag
    {
        int r = h & 1;
        const u64* sb0 = sBk + (r * 2 + 0) * 64;
        const u64* sb1 = sBk + (r * 2 + 1) * 64;
        const float* xq = x0 + (long)b * 1048576 + h * 256 + w0;
#pragma unroll 1
        for (int n = 0; n < 16; n++) {
            float4 xv = *reinterpret_cast<const float4*>(xq + n * 65536);
            u64 a0 = dup2(xv.x), a1 = dup2(xv.y), a2 = dup2(xv.z), a3 = dup2(xv.w);
            u64 e[4], od[4];
            ldw4(sb0 + n * 4, e);
            ldw4(sb1 + n * 4, od);
#pragma unroll
            for (int ip = 0; ip < 4; ip++) {
                dfma(acc[0][ip], e[ip], a0);
                dfma(acc[1][ip], od[ip], a1);
                dfma(acc[2][ip], e[ip], a2);
                dfma(acc[3][ip], od[ip], a3);
            }
        }
    }
    float bs = d_bscale[0];
    const float* bb = b0 + (long)ib * 65536 + h * 256 + w0;
    float* ob = out + (long)b * 1048576 + (long)ib * 65536 + h * 256 + w0;
#pragma unroll
    for (int ip = 0; ip < 4; ip++) {
        float2 f0 = up2(acc[0][ip]), f1 = up2(acc[1][ip]), f2 = up2(acc[2][ip]), f3 = up2(acc[3][ip]);
        float4 bv0 = *reinterpret_cast<const float4*>(bb + (2 * ip) * 65536);
        float4 bv1 = *reinterpret_cast<const float4*>(bb + (2 * ip + 1) * 65536);
        *(float4*)(ob + (2 * ip) * 65536) =
            make_float4(fmaf(bs, bv0.x, f0.x), fmaf(bs, bv0.y, f1.x),
                        fmaf(bs, bv0.z, f2.x), fmaf(bs, bv0.w, f3.x));
        *(float4*)(ob + (2 * ip + 1) * 65536) =
            make_float4(fmaf(bs, bv1.x, f0.y), fmaf(bs, bv1.y, f1.y),
                        fmaf(bs, bv1.z, f2.y), fmaf(bs, bv1.w, f3.y));
    }
}

// ---- Z1: out1 = -convt(Y1,W11) + diag(blk1,x1) + bias; 8 i-chan per block -----
__global__ __launch_bounds__(256, 3) void k_z1(const float* __restrict__ x1,
                                               const float* __restrict__ W11,
                                               const float* __restrict__ b1,
                                               float* __restrict__ out1) {
    extern __shared__ u64 sm[];   // sW 1152 + sB 64
    u64* sW = sm; u64* sB = sm + 1152;
    int t = threadIdx.x;
    int qq = blockIdx.z & 3, b = blockIdx.z >> 2;
    int group = qq >> 1, sub = (qq & 1) * 8;
    int igb = group * 16 + sub;   // global i-channel base (8 channels)
    for (int idx = t; idx < 1152; idx += 256) {
        int ip = idx & 3, rest = idx >> 2, tap = rest % 9, o = rest / 9;
        float wa = -__ldg(W11 + (o * 32 + igb + 2 * ip) * 9 + tap);
        float wb = -__ldg(W11 + (o * 32 + igb + 2 * ip + 1) * 9 + tap);
        sW[idx] = pk2(wa, wb);
    }
    for (int idx = t; idx < 64; idx += 256) {
        int ip = idx & 3, n = idx >> 2;
        float a0 = d_blk1[group * 256 + (sub + 2 * ip) * 16 + n];
        float a1 = d_blk1[group * 256 + (sub + 2 * ip + 1) * 16 + n];
        sB[idx] = pk2(a0, a1);
    }
    __syncthreads();
    int lane = t & 31, warp = t >> 5;
    int h = blockIdx.y * 8 + warp;
    int w0 = lane * 4;
    u64 acc[4][4];
#pragma unroll
    for (int p = 0; p < 4; p++)
#pragma unroll
        for (int ip = 0; ip < 4; ip++) acc[p][ip] = 0ull;
    const float* yb = d_Y1 + (long)b * 540800 + h * 130 + w0;
#pragma unroll 1
    for (int o = 0; o < 32; o++) {
        const float* yc = yb + o * 16900;
        float yv[3][6];
#pragma unroll
        for (int rr = 0; rr < 3; rr++) {
            float2 a = *reinterpret_cast<const float2*>(yc + rr * 130);
            float2 c = *reinterpret_cast<const float2*>(yc + rr * 130 + 2);
            float2 e = *reinterpret_cast<const float2*>(yc + rr * 130 + 4);
            yv[rr][0] = a.x; yv[rr][1] = a.y; yv[rr][2] = c.x;
            yv[rr][3] = c.y; yv[rr][4] = e.x; yv[rr][5] = e.y;
        }
        const u64* wbase = sW + o * 36;
#pragma unroll
        for (int dy = 0; dy < 3; dy++)
#pragma unroll
            for (int dx = 0; dx < 3; dx++) {
                u64 wr[4];
                ldw4(wbase + (dy * 3 + dx) * 4, wr);
#pragma unroll
                for (int p = 0; p < 4; p++) {
                    u64 a = dup2(yv[2 - dy][p + 2 - dx]);
#pragma unroll
                    for (int ip = 0; ip < 4; ip++) dfma(acc[p][ip], wr[ip], a);
                }
            }
    }
    // diag: x1 channels of this group (16 n)
    {
        const float* xq = x1 + (long)b * 524288 + (long)(group * 16) * 16384 + h * 128 + w0;
#pragma unroll 1
        for (int n = 0; n < 16; n++) {
            float4 xv = *reinterpret_cast<const float4*>(xq + n * 16384);
            u64 a0 = dup2(xv.x), a1 = dup2(xv.y), a2 = dup2(xv.z), a3 = dup2(xv.w);
            u64 e[4];
            ldw4(sB + n * 4, e);
#pragma unroll
            for (int ip = 0; ip < 4; ip++) {
                dfma(acc[0][ip], e[ip], a0);
                dfma(acc[1][ip], e[ip], a1);
                dfma(acc[2][ip], e[ip], a2);
                dfma(acc[3][ip], e[ip], a3);
            }
        }
    }
    float bs = d_bscale[1];
    const float* bb = b1 + (long)igb * 16384 + h * 128 + w0;
    float* ob = out1 + (long)b * 524288 + (long)igb * 16384 + h * 128 + w0;
#pragma unroll
    for (int ip = 0; ip < 4; ip++) {
        float2 f0 = up2(acc[0][ip]), f1 = up2(acc[1][ip]), f2 = up2(acc[2][ip]), f3 = up2(acc[3][ip]);
        float4 bv0 = *reinterpret_cast<const float4*>(bb + (2 * ip) * 16384);
        float4 bv1 = *reinterpret_cast<const float4*>(bb + (2 * ip + 1) * 16384);
        *(float4*)(ob + (2 * ip) * 16384) =
            make_float4(fmaf(bs, bv0.x, f0.x), fmaf(bs, bv0.y, f1.x),
                        fmaf(bs, bv0.z, f2.x), fmaf(bs, bv0.w, f3.x));
        *(float4*)(ob + (2 * ip + 1) * 16384) =
            make_float4(fmaf(bs, bv1.x, f0.y), fmaf(bs, bv1.y, f1.y),
                        fmaf(bs, bv1.z, f2.y), fmaf(bs, bv1.w, f3.y));
    }
}

// ---------------- launch ----------------
extern "C" void kernel_launch(void* const* d_in, const int* in_sizes, int n_in,
                              void* d_out, int out_size) {
    const float* x0  = (const float*)d_in[0];
    const float* x1  = (const float*)d_in[1];
    const float* W00 = (const float*)d_in[2];
    const float* W10 = (const float*)d_in[3];
    const float* W11 = (const float*)d_in[4];
    const float* b0  = (const float*)d_in[5];
    const float* b1  = (const float*)d_in[6];
    const float* g   = (const float*)d_in[7];
    float* out0 = (float*)d_out;
    float* out1 = out0 + (long)16 * 16 * 256 * 256;

    k_ssq<<<192, 256>>>(b0, b1);
    k_prep<<<6, 256>>>(W00, W10, W11, g);
    k_y0<<<dim3(66, 1, 32), 256, 576 * 8>>>(x0, W00);
    k_y1<<<dim3(17, 1, 64), 256, 1728 * 8>>>(x0, x1, W10, W11);
    k_z0<<<dim3(2, 32, 32), 256, 1984 * 8>>>(x0, W00, W10, b0, out0);
    k_z1<<<dim3(1, 16, 64), 256, 1216 * 8>>>(x1, W11, b1, out1);
}

// round 11
// speedup vs baseline: 1.0768x; 1.0768x over previous
#include <cuda_runtime.h>

// ---------------- scratch ----------------
__device__ __align__(16) float d_Y0[16 * 16 * 258 * 258];   // (B,16,258,258)
__device__ __align__(16) float d_Y1[16 * 32 * 130 * 130];   // (B,32,130,130)
__device__ float d_blk0[1024];   // [r2][c2][m16][n16]
__device__ float d_blk1[512];    // [g2][m16][n16]
__device__ float d_part[192];
__device__ float d_bscale[2];

typedef unsigned long long u64;

// ---------------- f32x2 helpers ----------------
__device__ __forceinline__ u64 pk2(float a, float b) {
    u64 r;
    asm("mov.b64 %0, {%1, %2};" : "=l"(r) : "r"(__float_as_uint(a)), "r"(__float_as_uint(b)));
    return r;
}
__device__ __forceinline__ u64 dup2(float a) { return pk2(a, a); }
__device__ __forceinline__ void dfma(u64& d, u64 a, u64 b) {
    asm("fma.rn.f32x2 %0, %1, %2, %0;" : "+l"(d) : "l"(a), "l"(b));
}
__device__ __forceinline__ float2 up2(u64 v) {
    unsigned lo, hi;
    asm("mov.b64 {%0, %1}, %2;" : "=r"(lo), "=r"(hi) : "l"(v));
    return make_float2(__uint_as_float(lo), __uint_as_float(hi));
}

// ---------------- P1: partial sum of squares for b0,b1 ----------------
__global__ __launch_bounds__(256) void k_ssq(const float* __restrict__ b0,
                                             const float* __restrict__ b1) {
    __shared__ float red[256];
    int bid = blockIdx.x, t = threadIdx.x;
    const float* src; long base;
    if (bid < 128) { src = b0; base = (long)bid * 8192; }
    else           { src = b1; base = (long)(bid - 128) * 8192; }
    float s = 0.f;
#pragma unroll
    for (int k = 0; k < 32; k++) { float v = __ldg(src + base + k * 256 + t); s += v * v; }
    red[t] = s; __syncthreads();
    for (int off = 128; off; off >>= 1) { if (t < off) red[t] += red[t + off]; __syncthreads(); }
    if (t == 0) d_part[bid] = red[0];
}

// ---------------- P2 (parallel, 6 blocks): bscale + Gram matrices --------------
__global__ __launch_bounds__(256) void k_prep(const float* __restrict__ W00,
                                              const float* __restrict__ W10,
                                              const float* __restrict__ W11,
                                              const float* __restrict__ g) {
    __shared__ float sw[9216];
    int blk = blockIdx.x, t = threadIdx.x;
    if (blk == 0 && t == 0) {
        float s0 = 0.f, s1 = 0.f;
        for (int i = 0; i < 128; i++) s0 += d_part[i];
        for (int i = 128; i < 192; i++) s1 += d_part[i];
        d_bscale[0] = __ldg(g) * rsqrtf(s0);
        d_bscale[1] = __ldg(g + 1) * rsqrtf(s1);
    }
    if (blk < 4) {
        for (int i = t; i < 2304; i += 256) sw[i] = __ldg(W00 + i);
        for (int i = t; i < 4608; i += 256) sw[2304 + i] = __ldg(W10 + i);
        __syncthreads();
        const float* s0 = sw;
        const float* s1 = sw + 2304;
        int e = blk * 256 + t;
        int n = e & 15, m = (e >> 4) & 15, c = (e >> 8) & 1, r = (e >> 9) & 1;
        float acc = 0.f;
        for (int o = 0; o < 16; o++) {
            const float* pm = s0 + (o * 16 + m) * 9;
            const float* pn = s0 + (o * 16 + n) * 9;
#pragma unroll
            for (int ij = 0; ij < 9; ij++) acc += pm[ij] * pn[ij];
        }
#pragma unroll
        for (int i1 = 0; i1 < 3; i1++) {
            if (((i1 + 1) & 1) != r) continue;
#pragma unroll
            for (int j1 = 0; j1 < 3; j1++) {
                if (((j1 + 1) & 1) != c) continue;
                int ij = i1 * 3 + j1;
                for (int o = 0; o < 32; o++)
                    acc += s1[(o * 16 + m) * 9 + ij] * s1[(o * 16 + n) * 9 + ij];
            }
        }
        d_blk0[e] = acc;   // ((r*2+c)*16+m)*16+n
    } else {
        for (int i = t; i < 9216; i += 256) sw[i] = __ldg(W11 + i);
        __syncthreads();
        int e = (blk - 4) * 256 + t;   // [0,512)
        int n = e & 15, m = (e >> 4) & 15, gg = e >> 8;
        float acc = 0.f;
        for (int o = 0; o < 32; o++) {
            const float* pm = sw + (o * 32 + gg * 16 + m) * 9;
            const float* pn = sw + (o * 32 + gg * 16 + n) * 9;
#pragma unroll
            for (int ij = 0; ij < 9; ij++) acc += pm[ij] * pn[ij];
        }
        d_blk1[e] = acc;   // (gg*16+m)*16+n
    }
}

// ---------------- Y0 = conv(x0, W00, s1, p2) -> (B,16,258,258) ----------------
__global__ __launch_bounds__(256, 2) void k_y0(const float* __restrict__ x0,
                                               const float* __restrict__ W00) {
    extern __shared__ u64 sm[];   // 1152: [(ic*9+tap)*8+ip]
    int t = threadIdx.x;
    for (int idx = t; idx < 1152; idx += 256) {
        int ip = idx & 7, rest = idx >> 3, tap = rest % 9, ic = rest / 9;
        float wa = __ldg(W00 + ((2 * ip) * 16 + ic) * 9 + tap);
        float wb = __ldg(W00 + ((2 * ip + 1) * 16 + ic) * 9 + tap);
        sm[idx] = pk2(wa, wb);
    }
    __syncthreads();
    int b = blockIdx.z;
    int item = blockIdx.x * 256 + t;
    int r = item / 65, q = item - r * 65;
    int w0 = q * 4;
    bool valid = (r < 258);
    u64 acc[4][8];
#pragma unroll
    for (int p = 0; p < 4; p++)
#pragma unroll
        for (int ip = 0; ip < 8; ip++) acc[p][ip] = 0ull;
    const float* xb = x0 + (long)b * 1048576;
#pragma unroll 1
    for (int ic = 0; ic < 16; ic++) {
        const float* xc = xb + ic * 65536;
        const u64* wbase = sm + ic * 72;
#pragma unroll
        for (int dy = 0; dy < 3; dy++) {
            int iy = r - 2 + dy;
            bool rowok = valid && iy >= 0 && iy < 256;
            float v[6];
#pragma unroll
            for (int j = 0; j < 6; j++) {
                int ix = w0 - 2 + j;
                v[j] = (rowok && ix >= 0 && ix < 256) ? __ldg(xc + iy * 256 + ix) : 0.f;
            }
#pragma unroll
            for (int dx = 0; dx < 3; dx++) {
                const u64* wp = wbase + (dy * 3 + dx) * 8;
                u64 wr[8];
#pragma unroll
                for (int ip = 0; ip < 8; ip++) wr[ip] = wp[ip];
#pragma unroll
                for (int p = 0; p < 4; p++) {
                    u64 a = dup2(v[p + dx]);
#pragma unroll
                    for (int ip = 0; ip < 8; ip++) dfma(acc[p][ip], wr[ip], a);
                }
            }
        }
    }
    if (valid) {
        float* yb = d_Y0 + (long)b * 1065024 + r * 258 + w0;
        if (w0 + 4 <= 258) {
#pragma unroll
            for (int ip = 0; ip < 8; ip++) {
                float2 f0 = up2(acc[0][ip]), f1 = up2(acc[1][ip]), f2 = up2(acc[2][ip]), f3 = up2(acc[3][ip]);
                yb[(2 * ip) * 66564 + 0] = f0.x; yb[(2 * ip) * 66564 + 1] = f1.x;
                yb[(2 * ip) * 66564 + 2] = f2.x; yb[(2 * ip) * 66564 + 3] = f3.x;
                yb[(2 * ip + 1) * 66564 + 0] = f0.y; yb[(2 * ip + 1) * 66564 + 1] = f1.y;
                yb[(2 * ip + 1) * 66564 + 2] = f2.y; yb[(2 * ip + 1) * 66564 + 3] = f3.y;
            }
        } else {
#pragma unroll
            for (int p = 0; p < 4; p++) {
                if (w0 + p >= 258) break;
#pragma unroll
                for (int ip = 0; ip < 8; ip++) {
                    float2 f = up2(acc[p][ip]);
                    yb[(2 * ip) * 66564 + p] = f.x;
                    yb[(2 * ip + 1) * 66564 + p] = f.y;
                }
            }
        }
    }
}

// ------- Y1 = conv(x0,W10,s2,p3) + conv(x1,W11,s1,p2) -> (B,32,130,130) -------
__global__ __launch_bounds__(256, 2) void k_y1(const float* __restrict__ x0,
                                               const float* __restrict__ x1,
                                               const float* __restrict__ W10,
                                               const float* __restrict__ W11) {
    extern __shared__ u64 sm[];   // sA 1152 + sB 2304
    u64* sA = sm; u64* sB2 = sm + 1152;
    int t = threadIdx.x;
    int half = blockIdx.z & 1, b = blockIdx.z >> 1;
    for (int idx = t; idx < 1152; idx += 256) {
        int ip = idx & 7, rest = idx >> 3, tap = rest % 9, ic = rest / 9;
        float wa = __ldg(W10 + ((half * 16 + 2 * ip) * 16 + ic) * 9 + tap);
        float wb = __ldg(W10 + ((half * 16 + 2 * ip + 1) * 16 + ic) * 9 + tap);
        sA[idx] = pk2(wa, wb);
    }
    for (int idx = t; idx < 2304; idx += 256) {
        int ip = idx & 7, rest = idx >> 3, tap = rest % 9, ic = rest / 9;
        float wa = __ldg(W11 + ((half * 16 + 2 * ip) * 32 + ic) * 9 + tap);
        float wb = __ldg(W11 + ((half * 16 + 2 * ip + 1) * 32 + ic) * 9 + tap);
        sB2[idx] = pk2(wa, wb);
    }
    __syncthreads();
    int item = blockIdx.x * 256 + t;
    int u = item / 33, q = item - u * 33;
    int v0 = q * 4;
    bool valid = (u < 130);
    u64 acc[4][8];
#pragma unroll
    for (int p = 0; p < 4; p++)
#pragma unroll
        for (int ip = 0; ip < 8; ip++) acc[p][ip] = 0ull;
    const float* xa = x0 + (long)b * 1048576;
#pragma unroll 1
    for (int ic = 0; ic < 16; ic++) {
        const float* xc = xa + ic * 65536;
        const u64* wbase = sA + ic * 72;
#pragma unroll
        for (int dy = 0; dy < 3; dy++) {
            int iy = 2 * u - 3 + dy;
            bool rowok = valid && iy >= 0 && iy < 256;
            float v[9];
#pragma unroll
            for (int j = 0; j < 9; j++) {
                int ix = 2 * v0 - 3 + j;
                v[j] = (rowok && ix >= 0 && ix < 256) ? __ldg(xc + iy * 256 + ix) : 0.f;
            }
#pragma unroll
            for (int dx = 0; dx < 3; dx++) {
                const u64* wp = wbase + (dy * 3 + dx) * 8;
                u64 wr[8];
#pragma unroll
                for (int ip = 0; ip < 8; ip++) wr[ip] = wp[ip];
#pragma unroll
                for (int p = 0; p < 4; p++) {
                    u64 a = dup2(v[2 * p + dx]);
#pragma unroll
                    for (int ip = 0; ip < 8; ip++) dfma(acc[p][ip], wr[ip], a);
                }
            }
        }
    }
    const float* xb1 = x1 + (long)b * 524288;
#pragma unroll 1
    for (int ic = 0; ic < 32; ic++) {
        const float* xc = xb1 + ic * 16384;
        const u64* wbase = sB2 + ic * 72;
#pragma unroll
        for (int dy = 0; dy < 3; dy++) {
            int iy = u - 2 + dy;
            bool rowok = valid && iy >= 0 && iy < 128;
            float v[6];
#pragma unroll
            for (int j = 0; j < 6; j++) {
                int ix = v0 - 2 + j;
                v[j] = (rowok && ix >= 0 && ix < 128) ? __ldg(xc + iy * 128 + ix) : 0.f;
            }
#pragma unroll
            for (int dx = 0; dx < 3; dx++) {
                const u64* wp = wbase + (dy * 3 + dx) * 8;
                u64 wr[8];
#pragma unroll
                for (int ip = 0; ip < 8; ip++) wr[ip] = wp[ip];
#pragma unroll
                for (int p = 0; p < 4; p++) {
                    u64 a = dup2(v[p + dx]);
#pragma unroll
                    for (int ip = 0; ip < 8; ip++) dfma(acc[p][ip], wr[ip], a);
                }
            }
        }
    }
    if (valid) {
        float* yb = d_Y1 + (long)b * 540800 + (long)(half * 16) * 16900 + u * 130 + v0;
#pragma unroll
        for (int p = 0; p < 4; p++) {
            if (v0 + p >= 130) break;
#pragma unroll
            for (int ip = 0; ip < 8; ip++) {
                float2 f = up2(acc[p][ip]);
                yb[(2 * ip) * 16900 + p] = f.x;
                yb[(2 * ip + 1) * 16900 + p] = f.y;
            }
        }
    }
}

// ---- Z0: out0 = -convt(Y0,W00,s1,p2) - convt(Y1,W10,s2,p3,op1) + diag + bias --
__global__ __launch_bounds__(256, 2) void k_z0(const float* __restrict__ x0,
                                               const float* __restrict__ W00,
                                               const float* __restrict__ W10,
                                               const float* __restrict__ b0,
                                               float* __restrict__ out) {
    extern __shared__ u64 sm[];   // sW 1152 | sBk 512 | sT 2304
    u64* sW = sm; u64* sBk = sm + 1152; u64* sT = sm + 1664;
    int t = threadIdx.x;
    for (int idx = t; idx < 1152; idx += 256) {
        int ip = idx & 7, rest = idx >> 3, tap = rest % 9, o = rest / 9;
        float wa = -__ldg(W00 + (o * 16 + 2 * ip) * 9 + tap);
        float wb = -__ldg(W00 + (o * 16 + 2 * ip + 1) * 9 + tap);
        sW[idx] = pk2(wa, wb);
    }
    for (int idx = t; idx < 512; idx += 256) {
        int ip = idx & 7, n = (idx >> 3) & 15, rc = idx >> 7;
        float a0 = d_blk0[(rc * 16 + 2 * ip) * 16 + n];
        float a1 = d_blk0[(rc * 16 + 2 * ip + 1) * 16 + n];
        sBk[idx] = pk2(a0, a1);
    }
    for (int idx = t; idx < 2304; idx += 256) {
        int ip = idx & 7, rest = idx >> 3, o = rest & 31, tap = rest >> 5;
        float wa = -__ldg(W10 + (o * 16 + 2 * ip) * 9 + tap);
        float wb = -__ldg(W10 + (o * 16 + 2 * ip + 1) * 9 + tap);
        sT[idx] = pk2(wa, wb);
    }
    __syncthreads();
    int b = blockIdx.z, lane = t & 31, warp = t >> 5;
    int h = blockIdx.y * 8 + warp;
    int w0 = (blockIdx.x * 32 + lane) * 4;
    u64 acc[4][8];
#pragma unroll
    for (int p = 0; p < 4; p++)
#pragma unroll
        for (int ip = 0; ip < 8; ip++) acc[p][ip] = 0ull;

    // term1: -convt(Y0,W00)
    const float* yb = d_Y0 + (long)b * 1065024 + h * 258 + w0;
#pragma unroll 1
    for (int o = 0; o < 16; o++) {
        const float* yc = yb + o * 66564;
        float yv[3][6];
#pragma unroll
        for (int rr = 0; rr < 3; rr++) {
            float2 a = *reinterpret_cast<const float2*>(yc + rr * 258);
            float2 c = *reinterpret_cast<const float2*>(yc + rr * 258 + 2);
            float2 e = *reinterpret_cast<const float2*>(yc + rr * 258 + 4);
            yv[rr][0] = a.x; yv[rr][1] = a.y; yv[rr][2] = c.x;
            yv[rr][3] = c.y; yv[rr][4] = e.x; yv[rr][5] = e.y;
        }
        const u64* wbase = sW + o * 72;
#pragma unroll
        for (int dy = 0; dy < 3; dy++)
#pragma unroll
            for (int dx = 0; dx < 3; dx++) {
                const u64* wp = wbase + (dy * 3 + dx) * 8;
                u64 wr[8];
#pragma unroll
                for (int ip = 0; ip < 8; ip++) wr[ip] = wp[ip];
#pragma unroll
                for (int p = 0; p < 4; p++) {
                    u64 a = dup2(yv[2 - dy][p + 2 - dx]);
#pragma unroll
                    for (int ip = 0; ip < 8; ip++) dfma(acc[p][ip], wr[ip], a);
                }
            }
    }
    // term2: -convt(Y1,W10,s2,p3,op1)
    {
        int qc = (w0 >> 1) + 1;
        int hp = h & 1;
        int ntap = hp ? 2 : 1;
        int dy0 = hp ? 0 : 1;
        int qr0 = hp ? ((h + 3) >> 1) : ((h >> 1) + 1);
        int qr1 = (h + 1) >> 1;
        const float* y1b = d_Y1 + (long)b * 540800;
#pragma unroll 1
        for (int o = 0; o < 32; o++) {
            const float* yo = y1b + o * 16900;
            for (int tt = 0; tt < ntap; tt++) {
                int dy = tt ? 2 : dy0;
                int qr = tt ? qr1 : qr0;
                const float* yr = yo + qr * 130 + qc;
                float yA = __ldg(yr), yB = __ldg(yr + 1), yC = __ldg(yr + 2);
                u64 aA = dup2(yA), aB = dup2(yB), aC = dup2(yC);
                const u64* w0p = sT + ((dy * 3 + 0) * 32 + o) * 8;
                const u64* w1p = sT + ((dy * 3 + 1) * 32 + o) * 8;
                const u64* w2p = sT + ((dy * 3 + 2) * 32 + o) * 8;
#pragma unroll
                for (int ip = 0; ip < 8; ip++) {
                    u64 r0v = w0p[ip], r1v = w1p[ip], r2v = w2p[ip];
                    dfma(acc[0][ip], r1v, aA);
                    dfma(acc[1][ip], r0v, aB);
                    dfma(acc[1][ip], r2v, aA);
                    dfma(acc[2][ip], r1v, aB);
                    dfma(acc[3][ip], r0v, aC);
                    dfma(acc[3][ip], r2v, aB);
                }
            }
        }
    }
    // term3: +diag
    {
        int r = h & 1;
        const u64* sb0 = sBk + (r * 2 + 0) * 128;
        const u64* sb1 = sBk + (r * 2 + 1) * 128;
        const float* xq = x0 + (long)b * 1048576 + h * 256 + w0;
#pragma unroll 1
        for (int n = 0; n < 16; n++) {
            float4 xv = *reinterpret_cast<const float4*>(xq + n * 65536);
            u64 a0 = dup2(xv.x), a1 = dup2(xv.y), a2 = dup2(xv.z), a3 = dup2(xv.w);
            const u64* b0p = sb0 + n * 8;
            const u64* b1p = sb1 + n * 8;
#pragma unroll
            for (int ip = 0; ip < 8; ip++) {
                u64 e = b0p[ip], od = b1p[ip];
                dfma(acc[0][ip], e, a0);
                dfma(acc[1][ip], od, a1);
                dfma(acc[2][ip], e, a2);
                dfma(acc[3][ip], od, a3);
            }
        }
    }
    float bs = d_bscale[0];
    const float* bb = b0 + h * 256 + w0;
    float* ob = out + (long)b * 1048576 + h * 256 + w0;
#pragma unroll
    for (int ip = 0; ip < 8; ip++) {
        float2 f0 = up2(acc[0][ip]), f1 = up2(acc[1][ip]), f2 = up2(acc[2][ip]), f3 = up2(acc[3][ip]);
        float4 bv0 = *reinterpret_cast<const float4*>(bb + (2 * ip) * 65536);
        float4 bv1 = *reinterpret_cast<const float4*>(bb + (2 * ip + 1) * 65536);
        *(float4*)(ob + (2 * ip) * 65536) =
            make_float4(fmaf(bs, bv0.x, f0.x), fmaf(bs, bv0.y, f1.x),
                        fmaf(bs, bv0.z, f2.x), fmaf(bs, bv0.w, f3.x));
        *(float4*)(ob + (2 * ip + 1) * 65536) =
            make_float4(fmaf(bs, bv1.x, f0.y), fmaf(bs, bv1.y, f1.y),
                        fmaf(bs, bv1.z, f2.y), fmaf(bs, bv1.w, f3.y));
    }
}

// -------- Z1: out1 = -convt(Y1,W11,s1,p2) + diag(blk1,x1) + bias ---------------
__global__ __launch_bounds__(256, 2) void k_z1(const float* __restrict__ x1,
                                               const float* __restrict__ W11,
                                               const float* __restrict__ b1,
                                               float* __restrict__ out1) {
    extern __shared__ u64 sm[];   // sW 2304 + sB 128
    u64* sW = sm; u64* sB = sm + 2304;
    int t = threadIdx.x;
    int half = blockIdx.z & 1, b = blockIdx.z >> 1;
    for (int idx = t; idx < 2304; idx += 256) {
        int ip = idx & 7, rest = idx >> 3, tap = rest % 9, o = rest / 9;
        float wa = -__ldg(W11 + (o * 32 + half * 16 + 2 * ip) * 9 + tap);
        float wb = -__ldg(W11 + (o * 32 + half * 16 + 2 * ip + 1) * 9 + tap);
        sW[idx] = pk2(wa, wb);
    }
    for (int idx = t; idx < 128; idx += 256) {
        int ip = idx & 7, n = idx >> 3;
        float a0 = d_blk1[half * 256 + (2 * ip) * 16 + n];
        float a1 = d_blk1[half * 256 + (2 * ip + 1) * 16 + n];
        sB[idx] = pk2(a0, a1);
    }
    __syncthreads();
    int lane = t & 31, warp = t >> 5;
    int h = blockIdx.y * 8 + warp;
    int w0 = lane * 4;
    u64 acc[4][8];
#pragma unroll
    for (int p = 0; p < 4; p++)
#pragma unroll
        for (int ip = 0; ip < 8; ip++) acc[p][ip] = 0ull;
    const float* yb = d_Y1 + (long)b * 540800 + h * 130 + w0;
#pragma unroll 1
    for (int o = 0; o < 32; o++) {
        const float* yc = yb + o * 16900;
        float yv[3][6];
#pragma unroll
        for (int rr = 0; rr < 3; rr++) {
            float2 a = *reinterpret_cast<const float2*>(yc + rr * 130);
            float2 c = *reinterpret_cast<const float2*>(yc + rr * 130 + 2);
            float2 e = *reinterpret_cast<const float2*>(yc + rr * 130 + 4);
            yv[rr][0] = a.x; yv[rr][1] = a.y; yv[rr][2] = c.x;
            yv[rr][3] = c.y; yv[rr][4] = e.x; yv[rr][5] = e.y;
        }
        const u64* wbase = sW + o * 72;
#pragma unroll
        for (int dy = 0; dy < 3; dy++)
#pragma unroll
            for (int dx = 0; dx < 3; dx++) {
                const u64* wp = wbase + (dy * 3 + dx) * 8;
                u64 wr[8];
#pragma unroll
                for (int ip = 0; ip < 8; ip++) wr[ip] = wp[ip];
#pragma unroll
                for (int p = 0; p < 4; p++) {
                    u64 a = dup2(yv[2 - dy][p + 2 - dx]);
#pragma unroll
                    for (int ip = 0; ip < 8; ip++) dfma(acc[p][ip], wr[ip], a);
                }
            }
    }
    // diag
    {
        const float* xq = x1 + (long)b * 524288 + (long)(half * 16) * 16384 + h * 128 + w0;
#pragma unroll 1
        for (int n = 0; n < 16; n++) {
            float4 xv = *reinterpret_cast<const float4*>(xq + n * 16384);
            u64 a0 = dup2(xv.x), a1 = dup2(xv.y), a2 = dup2(xv.z), a3 = dup2(xv.w);
            const u64* bp = sB + n * 8;
#pragma unroll
            for (int ip = 0; ip < 8; ip++) {
                u64 e = bp[ip];
                dfma(acc[0][ip], e, a0);
                dfma(acc[1][ip], e, a1);
                dfma(acc[2][ip], e, a2);
                dfma(acc[3][ip], e, a3);
            }
        }
    }
    float bs = d_bscale[1];
    const float* bb = b1 + (long)(half * 16) * 16384 + h * 128 + w0;
    float* ob = out1 + (long)b * 524288 + (long)(half * 16) * 16384 + h * 128 + w0;
#pragma unroll
    for (int ip = 0; ip < 8; ip++) {
        float2 f0 = up2(acc[0][ip]), f1 = up2(acc[1][ip]), f2 = up2(acc[2][ip]), f3 = up2(acc[3][ip]);
        float4 bv0 = *reinterpret_cast<const float4*>(bb + (2 * ip) * 16384);
        float4 bv1 = *reinterpret_cast<const float4*>(bb + (2 * ip + 1) * 16384);
        *(float4*)(ob + (2 * ip) * 16384) =
            make_float4(fmaf(bs, bv0.x, f0.x), fmaf(bs, bv0.y, f1.x),
                        fmaf(bs, bv0.z, f2.x), fmaf(bs, bv0.w, f3.x));
        *(float4*)(ob + (2 * ip + 1) * 16384) =
            make_float4(fmaf(bs, bv1.x, f0.y), fmaf(bs, bv1.y, f1.y),
                        fmaf(bs, bv1.z, f2.y), fmaf(bs, bv1.w, f3.y));
    }
}

// ---------------- launch ----------------
extern "C" void kernel_launch(void* const* d_in, const int* in_sizes, int n_in,
                              void* d_out, int out_size) {
    const float* x0  = (const float*)d_in[0];
    const float* x1  = (const float*)d_in[1];
    const float* W00 = (const float*)d_in[2];
    const float* W10 = (const float*)d_in[3];
    const float* W11 = (const float*)d_in[4];
    const float* b0  = (const float*)d_in[5];
    const float* b1  = (const float*)d_in[6];
    const float* g   = (const float*)d_in[7];
    float* out0 = (float*)d_out;
    float* out1 = out0 + (long)16 * 16 * 256 * 256;

    k_ssq<<<192, 256>>>(b0, b1);
    k_prep<<<6, 256>>>(W00, W10, W11, g);
    k_y0<<<dim3(66, 1, 16), 256, 1152 * 8>>>(x0, W00);
    k_y1<<<dim3(17, 1, 32), 256, 3456 * 8>>>(x0, x1, W10, W11);
    k_z0<<<dim3(2, 32, 16), 256, 3968 * 8>>>(x0, W00, W10, b0, out0);
    k_z1<<<dim3(1, 16, 32), 256, 2432 * 8>>>(x1, W11, b1, out1);
}

// round 12
// speedup vs baseline: 1.0843x; 1.0070x over previous
#include <cuda_runtime.h>

// ---------------- scratch ----------------
__device__ __align__(16) float d_Y0[16 * 16 * 258 * 258];   // (B,16,258,258)
__device__ __align__(16) float d_Y1[16 * 32 * 130 * 130];   // (B,32,130,130)
__device__ float d_blk0[1024];   // [r2][c2][m16][n16]
__device__ float d_blk1[512];    // [g2][m16][n16]
__device__ float d_part[192];
__device__ float d_bscale[2];

typedef unsigned long long u64;

// ---------------- f32x2 helpers ----------------
__device__ __forceinline__ u64 pk2(float a, float b) {
    u64 r;
    asm("mov.b64 %0, {%1, %2};" : "=l"(r) : "r"(__float_as_uint(a)), "r"(__float_as_uint(b)));
    return r;
}
__device__ __forceinline__ u64 dup2(float a) { return pk2(a, a); }
__device__ __forceinline__ void dfma(u64& d, u64 a, u64 b) {
    asm("fma.rn.f32x2 %0, %1, %2, %0;" : "+l"(d) : "l"(a), "l"(b));
}
__device__ __forceinline__ float2 up2(u64 v) {
    unsigned lo, hi;
    asm("mov.b64 {%0, %1}, %2;" : "=r"(lo), "=r"(hi) : "l"(v));
    return make_float2(__uint_as_float(lo), __uint_as_float(hi));
}
__device__ __forceinline__ void ldw8(const u64* p, u64 wr[8]) {
    const ulonglong2* q = (const ulonglong2*)p;
    ulonglong2 a = q[0], b = q[1], c = q[2], d = q[3];
    wr[0] = a.x; wr[1] = a.y; wr[2] = b.x; wr[3] = b.y;
    wr[4] = c.x; wr[5] = c.y; wr[6] = d.x; wr[7] = d.y;
}

// ---------------- P1: partial sum of squares for b0,b1 ----------------
__global__ __launch_bounds__(256) void k_ssq(const float* __restrict__ b0,
                                             const float* __restrict__ b1) {
    __shared__ float red[256];
    int bid = blockIdx.x, t = threadIdx.x;
    const float* src; long base;
    if (bid < 128) { src = b0; base = (long)bid * 8192; }
    else           { src = b1; base = (long)(bid - 128) * 8192; }
    float s = 0.f;
#pragma unroll
    for (int k = 0; k < 32; k++) { float v = __ldg(src + base + k * 256 + t); s += v * v; }
    red[t] = s; __syncthreads();
    for (int off = 128; off; off >>= 1) { if (t < off) red[t] += red[t + off]; __syncthreads(); }
    if (t == 0) d_part[bid] = red[0];
}

// ---------------- P2 (parallel, 6 blocks): bscale + Gram matrices --------------
__global__ __launch_bounds__(256) void k_prep(const float* __restrict__ W00,
                                              const float* __restrict__ W10,
                                              const float* __restrict__ W11,
                                              const float* __restrict__ g) {
    __shared__ float sw[9216];
    int blk = blockIdx.x, t = threadIdx.x;
    if (blk == 0 && t == 0) {
        float s0 = 0.f, s1 = 0.f;
        for (int i = 0; i < 128; i++) s0 += d_part[i];
        for (int i = 128; i < 192; i++) s1 += d_part[i];
        d_bscale[0] = __ldg(g) * rsqrtf(s0);
        d_bscale[1] = __ldg(g + 1) * rsqrtf(s1);
    }
    if (blk < 4) {
        for (int i = t; i < 2304; i += 256) sw[i] = __ldg(W00 + i);
        for (int i = t; i < 4608; i += 256) sw[2304 + i] = __ldg(W10 + i);
        __syncthreads();
        const float* s0 = sw;
        const float* s1 = sw + 2304;
        int e = blk * 256 + t;
        int n = e & 15, m = (e >> 4) & 15, c = (e >> 8) & 1, r = (e >> 9) & 1;
        float acc = 0.f;
        for (int o = 0; o < 16; o++) {
            const float* pm = s0 + (o * 16 + m) * 9;
            const float* pn = s0 + (o * 16 + n) * 9;
#pragma unroll
            for (int ij = 0; ij < 9; ij++) acc += pm[ij] * pn[ij];
        }
#pragma unroll
        for (int i1 = 0; i1 < 3; i1++) {
            if (((i1 + 1) & 1) != r) continue;
#pragma unroll
            for (int j1 = 0; j1 < 3; j1++) {
                if (((j1 + 1) & 1) != c) continue;
                int ij = i1 * 3 + j1;
                for (int o = 0; o < 32; o++)
                    acc += s1[(o * 16 + m) * 9 + ij] * s1[(o * 16 + n) * 9 + ij];
            }
        }
        d_blk0[e] = acc;   // ((r*2+c)*16+m)*16+n
    } else {
        for (int i = t; i < 9216; i += 256) sw[i] = __ldg(W11 + i);
        __syncthreads();
        int e = (blk - 4) * 256 + t;   // [0,512)
        int n = e & 15, m = (e >> 4) & 15, gg = e >> 8;
        float acc = 0.f;
        for (int o = 0; o < 32; o++) {
            const float* pm = sw + (o * 32 + gg * 16 + m) * 9;
            const float* pn = sw + (o * 32 + gg * 16 + n) * 9;
#pragma unroll
            for (int ij = 0; ij < 9; ij++) acc += pm[ij] * pn[ij];
        }
        d_blk1[e] = acc;   // (gg*16+m)*16+n
    }
}

// ---------------- Y0 = conv(x0, W00, s1, p2); dy-outer + ic prefetch ----------
__global__ __launch_bounds__(256, 2) void k_y0(const float* __restrict__ x0,
                                               const float* __restrict__ W00) {
    extern __shared__ u64 sm[];   // 1152: [(ic*9+tap)*8+ip]
    int t = threadIdx.x;
    for (int idx = t; idx < 1152; idx += 256) {
        int ip = idx & 7, rest = idx >> 3, tap = rest % 9, ic = rest / 9;
        float wa = __ldg(W00 + ((2 * ip) * 16 + ic) * 9 + tap);
        float wb = __ldg(W00 + ((2 * ip + 1) * 16 + ic) * 9 + tap);
        sm[idx] = pk2(wa, wb);
    }
    __syncthreads();
    int b = blockIdx.z;
    int item = blockIdx.x * 256 + t;
    int r = item / 65, q = item - r * 65;
    int w0 = q * 4;
    bool valid = (r < 258);
    u64 acc[4][8];
#pragma unroll
    for (int p = 0; p < 4; p++)
#pragma unroll
        for (int ip = 0; ip < 8; ip++) acc[p][ip] = 0ull;
    const float* xb = x0 + (long)b * 1048576;
#pragma unroll 1
    for (int dy = 0; dy < 3; dy++) {
        int iy = r - 2 + dy;
        bool rowok = valid && iy >= 0 && iy < 256;
        const float* rowp = xb + iy * 256;
        float v[6];
#pragma unroll
        for (int j = 0; j < 6; j++) {
            int ix = w0 - 2 + j;
            v[j] = (rowok && ix >= 0 && ix < 256) ? __ldg(rowp + ix) : 0.f;
        }
#pragma unroll 1
        for (int ic = 0; ic < 16; ic++) {
            int icn = ic < 15 ? ic + 1 : ic;
            const float* nrow = xb + icn * 65536 + iy * 256;
            float nv[6];
#pragma unroll
            for (int j = 0; j < 6; j++) {
                int ix = w0 - 2 + j;
                nv[j] = (rowok && ix >= 0 && ix < 256) ? __ldg(nrow + ix) : 0.f;
            }
            const u64* wbase = sm + ic * 72 + dy * 24;
#pragma unroll
            for (int dx = 0; dx < 3; dx++) {
                u64 wr[8];
                ldw8(wbase + dx * 8, wr);
#pragma unroll
                for (int p = 0; p < 4; p++) {
                    u64 a = dup2(v[p + dx]);
#pragma unroll
                    for (int ip = 0; ip < 8; ip++) dfma(acc[p][ip], wr[ip], a);
                }
            }
#pragma unroll
            for (int j = 0; j < 6; j++) v[j] = nv[j];
        }
    }
    if (valid) {
        float* yb = d_Y0 + (long)b * 1065024 + r * 258 + w0;
        if (w0 + 4 <= 258) {
#pragma unroll
            for (int ip = 0; ip < 8; ip++) {
                float2 f0 = up2(acc[0][ip]), f1 = up2(acc[1][ip]), f2 = up2(acc[2][ip]), f3 = up2(acc[3][ip]);
                yb[(2 * ip) * 66564 + 0] = f0.x; yb[(2 * ip) * 66564 + 1] = f1.x;
                yb[(2 * ip) * 66564 + 2] = f2.x; yb[(2 * ip) * 66564 + 3] = f3.x;
                yb[(2 * ip + 1) * 66564 + 0] = f0.y; yb[(2 * ip + 1) * 66564 + 1] = f1.y;
                yb[(2 * ip + 1) * 66564 + 2] = f2.y; yb[(2 * ip + 1) * 66564 + 3] = f3.y;
            }
        } else {
#pragma unroll
            for (int p = 0; p < 4; p++) {
                if (w0 + p >= 258) break;
#pragma unroll
                for (int ip = 0; ip < 8; ip++) {
                    float2 f = up2(acc[p][ip]);
                    yb[(2 * ip) * 66564 + p] = f.x;
                    yb[(2 * ip + 1) * 66564 + p] = f.y;
                }
            }
        }
    }
}

// ------- Y1 = conv(x0,W10,s2,p3) + conv(x1,W11,s1,p2); ic prefetch ------------
__global__ __launch_bounds__(256, 2) void k_y1(const float* __restrict__ x0,
                                               const float* __restrict__ x1,
                                               const float* __restrict__ W10,
                                               const float* __restrict__ W11) {
    extern __shared__ u64 sm[];   // sA 1152 + sB 2304
    u64* sA = sm; u64* sB2 = sm + 1152;
    int t = threadIdx.x;
    int half = blockIdx.z & 1, b = blockIdx.z >> 1;
    for (int idx = t; idx < 1152; idx += 256) {
        int ip = idx & 7, rest = idx >> 3, tap = rest % 9, ic = rest / 9;
        float wa = __ldg(W10 + ((half * 16 + 2 * ip) * 16 + ic) * 9 + tap);
        float wb = __ldg(W10 + ((half * 16 + 2 * ip + 1) * 16 + ic) * 9 + tap);
        sA[idx] = pk2(wa, wb);
    }
    for (int idx = t; idx < 2304; idx += 256) {
        int ip = idx & 7, rest = idx >> 3, tap = rest % 9, ic = rest / 9;
        float wa = __ldg(W11 + ((half * 16 + 2 * ip) * 32 + ic) * 9 + tap);
        float wb = __ldg(W11 + ((half * 16 + 2 * ip + 1) * 32 + ic) * 9 + tap);
        sB2[idx] = pk2(wa, wb);
    }
    __syncthreads();
    int item = blockIdx.x * 256 + t;
    int u = item / 33, q = item - u * 33;
    int v0 = q * 4;
    bool valid = (u < 130);
    u64 acc[4][8];
#pragma unroll
    for (int p = 0; p < 4; p++)
#pragma unroll
        for (int ip = 0; ip < 8; ip++) acc[p][ip] = 0ull;
    // phase A: stride-2 over x0; dy-outer, ic-inner with prefetch
    const float* xa = x0 + (long)b * 1048576;
#pragma unroll 1
    for (int dy = 0; dy < 3; dy++) {
        int iy = 2 * u - 3 + dy;
        bool rowok = valid && iy >= 0 && iy < 256;
        const float* rowp = xa + iy * 256;
        float v[9];
#pragma unroll
        for (int j = 0; j < 9; j++) {
            int ix = 2 * v0 - 3 + j;
            v[j] = (rowok && ix >= 0 && ix < 256) ? __ldg(rowp + ix) : 0.f;
        }
#pragma unroll 1
        for (int ic = 0; ic < 16; ic++) {
            int icn = ic < 15 ? ic + 1 : ic;
            const float* nrow = xa + icn * 65536 + iy * 256;
            float nv[9];
#pragma unroll
            for (int j = 0; j < 9; j++) {
                int ix = 2 * v0 - 3 + j;
                nv[j] = (rowok && ix >= 0 && ix < 256) ? __ldg(nrow + ix) : 0.f;
            }
            const u64* wbase = sA + ic * 72 + dy * 24;
#pragma unroll
            for (int dx = 0; dx < 3; dx++) {
                u64 wr[8];
                ldw8(wbase + dx * 8, wr);
#pragma unroll
                for (int p = 0; p < 4; p++) {
                    u64 a = dup2(v[2 * p + dx]);
#pragma unroll
                    for (int ip = 0; ip < 8; ip++) dfma(acc[p][ip], wr[ip], a);
                }
            }
#pragma unroll
            for (int j = 0; j < 9; j++) v[j] = nv[j];
        }
    }
    // phase B: stride-1 over x1
    const float* xb1 = x1 + (long)b * 524288;
#pragma unroll 1
    for (int dy = 0; dy < 3; dy++) {
        int iy = u - 2 + dy;
        bool rowok = valid && iy >= 0 && iy < 128;
        const float* rowp = xb1 + iy * 128;
        float v[6];
#pragma unroll
        for (int j = 0; j < 6; j++) {
            int ix = v0 - 2 + j;
            v[j] = (rowok && ix >= 0 && ix < 128) ? __ldg(rowp + ix) : 0.f;
        }
#pragma unroll 1
        for (int ic = 0; ic < 32; ic++) {
            int icn = ic < 31 ? ic + 1 : ic;
            const float* nrow = xb1 + icn * 16384 + iy * 128;
            float nv[6];
#pragma unroll
            for (int j = 0; j < 6; j++) {
                int ix = v0 - 2 + j;
                nv[j] = (rowok && ix >= 0 && ix < 128) ? __ldg(nrow + ix) : 0.f;
            }
            const u64* wbase = sB2 + ic * 72 + dy * 24;
#pragma unroll
            for (int dx = 0; dx < 3; dx++) {
                u64 wr[8];
                ldw8(wbase + dx * 8, wr);
#pragma unroll
                for (int p = 0; p < 4; p++) {
                    u64 a = dup2(v[p + dx]);
#pragma unroll
                    for (int ip = 0; ip < 8; ip++) dfma(acc[p][ip], wr[ip], a);
                }
            }
#pragma unroll
            for (int j = 0; j < 6; j++) v[j] = nv[j];
        }
    }
    if (valid) {
        float* yb = d_Y1 + (long)b * 540800 + (long)(half * 16) * 16900 + u * 130 + v0;
#pragma unroll
        for (int p = 0; p < 4; p++) {
            if (v0 + p >= 130) break;
#pragma unroll
            for (int ip = 0; ip < 8; ip++) {
                float2 f = up2(acc[p][ip]);
                yb[(2 * ip) * 16900 + p] = f.x;
                yb[(2 * ip + 1) * 16900 + p] = f.y;
            }
        }
    }
}

// ---- Z0: out0 = -convt(Y0,W00,s1,p2) - convt(Y1,W10,s2,p3,op1) + diag + bias --
__global__ __launch_bounds__(256, 2) void k_z0(const float* __restrict__ x0,
                                               const float* __restrict__ W00,
                                               const float* __restrict__ W10,
                                               const float* __restrict__ b0,
                                               float* __restrict__ out) {
    extern __shared__ u64 sm[];   // sW 1152 | sBk 512 | sT 2304
    u64* sW = sm; u64* sBk = sm + 1152; u64* sT = sm + 1664;
    int t = threadIdx.x;
    for (int idx = t; idx < 1152; idx += 256) {
        int ip = idx & 7, rest = idx >> 3, tap = rest % 9, o = rest / 9;
        float wa = -__ldg(W00 + (o * 16 + 2 * ip) * 9 + tap);
        float wb = -__ldg(W00 + (o * 16 + 2 * ip + 1) * 9 + tap);
        sW[idx] = pk2(wa, wb);
    }
    for (int idx = t; idx < 512; idx += 256) {
        int ip = idx & 7, n = (idx >> 3) & 15, rc = idx >> 7;
        float a0 = d_blk0[(rc * 16 + 2 * ip) * 16 + n];
        float a1 = d_blk0[(rc * 16 + 2 * ip + 1) * 16 + n];
        sBk[idx] = pk2(a0, a1);
    }
    for (int idx = t; idx < 2304; idx += 256) {
        int ip = idx & 7, rest = idx >> 3, o = rest & 31, tap = rest >> 5;
        float wa = -__ldg(W10 + (o * 16 + 2 * ip) * 9 + tap);
        float wb = -__ldg(W10 + (o * 16 + 2 * ip + 1) * 9 + tap);
        sT[idx] = pk2(wa, wb);
    }
    __syncthreads();
    int b = blockIdx.z, lane = t & 31, warp = t >> 5;
    int h = blockIdx.y * 8 + warp;
    int w0 = (blockIdx.x * 32 + lane) * 4;
    u64 acc[4][8];
#pragma unroll
    for (int p = 0; p < 4; p++)
#pragma unroll
        for (int ip = 0; ip < 8; ip++) acc[p][ip] = 0ull;

    // term1: -convt(Y0,W00)
    const float* yb = d_Y0 + (long)b * 1065024 + h * 258 + w0;
#pragma unroll 1
    for (int o = 0; o < 16; o++) {
        const float* yc = yb + o * 66564;
        float yv[3][6];
#pragma unroll
        for (int rr = 0; rr < 3; rr++) {
            float2 a = *reinterpret_cast<const float2*>(yc + rr * 258);
            float2 c = *reinterpret_cast<const float2*>(yc + rr * 258 + 2);
            float2 e = *reinterpret_cast<const float2*>(yc + rr * 258 + 4);
            yv[rr][0] = a.x; yv[rr][1] = a.y; yv[rr][2] = c.x;
            yv[rr][3] = c.y; yv[rr][4] = e.x; yv[rr][5] = e.y;
        }
        const u64* wbase = sW + o * 72;
#pragma unroll
        for (int dy = 0; dy < 3; dy++)
#pragma unroll
            for (int dx = 0; dx < 3; dx++) {
                const u64* wp = wbase + (dy * 3 + dx) * 8;
                u64 wr[8];
#pragma unroll
                for (int ip = 0; ip < 8; ip++) wr[ip] = wp[ip];
#pragma unroll
                for (int p = 0; p < 4; p++) {
                    u64 a = dup2(yv[2 - dy][p + 2 - dx]);
#pragma unroll
                    for (int ip = 0; ip < 8; ip++) dfma(acc[p][ip], wr[ip], a);
                }
            }
    }
    // term2: -convt(Y1,W10,s2,p3,op1)
    {
        int qc = (w0 >> 1) + 1;
        int hp = h & 1;
        int ntap = hp ? 2 : 1;
        int dy0 = hp ? 0 : 1;
        int qr0 = hp ? ((h + 3) >> 1) : ((h >> 1) + 1);
        int qr1 = (h + 1) >> 1;
        const float* y1b = d_Y1 + (long)b * 540800;
#pragma unroll 1
        for (int o = 0; o < 32; o++) {
            const float* yo = y1b + o * 16900;
            for (int tt = 0; tt < ntap; tt++) {
                int dy = tt ? 2 : dy0;
                int qr = tt ? qr1 : qr0;
                const float* yr = yo + qr * 130 + qc;
                float yA = __ldg(yr), yB = __ldg(yr + 1), yC = __ldg(yr + 2);
                u64 aA = dup2(yA), aB = dup2(yB), aC = dup2(yC);
                const u64* w0p = sT + ((dy * 3 + 0) * 32 + o) * 8;
                const u64* w1p = sT + ((dy * 3 + 1) * 32 + o) * 8;
                const u64* w2p = sT + ((dy * 3 + 2) * 32 + o) * 8;
#pragma unroll
                for (int ip = 0; ip < 8; ip++) {
                    u64 r0v = w0p[ip], r1v = w1p[ip], r2v = w2p[ip];
                    dfma(acc[0][ip], r1v, aA);
                    dfma(acc[1][ip], r0v, aB);
                    dfma(acc[1][ip], r2v, aA);
                    dfma(acc[2][ip], r1v, aB);
                    dfma(acc[3][ip], r0v, aC);
                    dfma(acc[3][ip], r2v, aB);
                }
            }
        }
    }
    // term3: +diag
    {
        int r = h & 1;
        const u64* sb0 = sBk + (r * 2 + 0) * 128;
        const u64* sb1 = sBk + (r * 2 + 1) * 128;
        const float* xq = x0 + (long)b * 1048576 + h * 256 + w0;
#pragma unroll 1
        for (int n = 0; n < 16; n++) {
            float4 xv = *reinterpret_cast<const float4*>(xq + n * 65536);
            u64 a0 = dup2(xv.x), a1 = dup2(xv.y), a2 = dup2(xv.z), a3 = dup2(xv.w);
            const u64* b0p = sb0 + n * 8;
            const u64* b1p = sb1 + n * 8;
#pragma unroll
            for (int ip = 0; ip < 8; ip++) {
                u64 e = b0p[ip], od = b1p[ip];
                dfma(acc[0][ip], e, a0);
                dfma(acc[1][ip], od, a1);
                dfma(acc[2][ip], e, a2);
                dfma(acc[3][ip], od, a3);
            }
        }
    }
    float bs = d_bscale[0];
    const float* bb = b0 + h * 256 + w0;
    float* ob = out + (long)b * 1048576 + h * 256 + w0;
#pragma unroll
    for (int ip = 0; ip < 8; ip++) {
        float2 f0 = up2(acc[0][ip]), f1 = up2(acc[1][ip]), f2 = up2(acc[2][ip]), f3 = up2(acc[3][ip]);
        float4 bv0 = *reinterpret_cast<const float4*>(bb + (2 * ip) * 65536);
        float4 bv1 = *reinterpret_cast<const float4*>(bb + (2 * ip + 1) * 65536);
        *(float4*)(ob + (2 * ip) * 65536) =
            make_float4(fmaf(bs, bv0.x, f0.x), fmaf(bs, bv0.y, f1.x),
                        fmaf(bs, bv0.z, f2.x), fmaf(bs, bv0.w, f3.x));
        *(float4*)(ob + (2 * ip + 1) * 65536) =
            make_float4(fmaf(bs, bv1.x, f0.y), fmaf(bs, bv1.y, f1.y),
                        fmaf(bs, bv1.z, f2.y), fmaf(bs, bv1.w, f3.y));
    }
}

// -------- Z1: out1 = -convt(Y1,W11,s1,p2) + diag(blk1,x1) + bias ---------------
__global__ __launch_bounds__(256, 2) void k_z1(const float* __restrict__ x1,
                                               const float* __restrict__ W11,
                                               const float* __restrict__ b1,
                                               float* __restrict__ out1) {
    extern __shared__ u64 sm[];   // sW 2304 + sB 128
    u64* sW = sm; u64* sB = sm + 2304;
    int t = threadIdx.x;
    int half = blockIdx.z & 1, b = blockIdx.z >> 1;
    for (int idx = t; idx < 2304; idx += 256) {
        int ip = idx & 7, rest = idx >> 3, tap = rest % 9, o = rest / 9;
        float wa = -__ldg(W11 + (o * 32 + half * 16 + 2 * ip) * 9 + tap);
        float wb = -__ldg(W11 + (o * 32 + half * 16 + 2 * ip + 1) * 9 + tap);
        sW[idx] = pk2(wa, wb);
    }
    for (int idx = t; idx < 128; idx += 256) {
        int ip = idx & 7, n = idx >> 3;
        float a0 = d_blk1[half * 256 + (2 * ip) * 16 + n];
        float a1 = d_blk1[half * 256 + (2 * ip + 1) * 16 + n];
        sB[idx] = pk2(a0, a1);
    }
    __syncthreads();
    int lane = t & 31, warp = t >> 5;
    int h = blockIdx.y * 8 + warp;
    int w0 = lane * 4;
    u64 acc[4][8];
#pragma unroll
    for (int p = 0; p < 4; p++)
#pragma unroll
        for (int ip = 0; ip < 8; ip++) acc[p][ip] = 0ull;
    const float* yb = d_Y1 + (long)b * 540800 + h * 130 + w0;
#pragma unroll 1
    for (int o = 0; o < 32; o++) {
        const float* yc = yb + o * 16900;
        float yv[3][6];
#pragma unroll
        for (int rr = 0; rr < 3; rr++) {
            float2 a = *reinterpret_cast<const float2*>(yc + rr * 130);
            float2 c = *reinterpret_cast<const float2*>(yc + rr * 130 + 2);
            float2 e = *reinterpret_cast<const float2*>(yc + rr * 130 + 4);
            yv[rr][0] = a.x; yv[rr][1] = a.y; yv[rr][2] = c.x;
            yv[rr][3] = c.y; yv[rr][4] = e.x; yv[rr][5] = e.y;
        }
        const u64* wbase = sW + o * 72;
#pragma unroll
        for (int dy = 0; dy < 3; dy++)
#pragma unroll
            for (int dx = 0; dx < 3; dx++) {
                const u64* wp = wbase + (dy * 3 + dx) * 8;
                u64 wr[8];
#pragma unroll
                for (int ip = 0; ip < 8; ip++) wr[ip] = wp[ip];
#pragma unroll
                for (int p = 0; p < 4; p++) {
                    u64 a = dup2(yv[2 - dy][p + 2 - dx]);
#pragma unroll
                    for (int ip = 0; ip < 8; ip++) dfma(acc[p][ip], wr[ip], a);
                }
            }
    }
    // diag
    {
        const float* xq = x1 + (long)b * 524288 + (long)(half * 16) * 16384 + h * 128 + w0;
#pragma unroll 1
        for (int n = 0; n < 16; n++) {
            float4 xv = *reinterpret_cast<const float4*>(xq + n * 16384);
            u64 a0 = dup2(xv.x), a1 = dup2(xv.y), a2 = dup2(xv.z), a3 = dup2(xv.w);
            const u64* bp = sB + n * 8;
#pragma unroll
            for (int ip = 0; ip < 8; ip++) {
                u64 e = bp[ip];
                dfma(acc[0][ip], e, a0);
                dfma(acc[1][ip], e, a1);
                dfma(acc[2][ip], e, a2);
                dfma(acc[3][ip], e, a3);
            }
        }
    }
    float bs = d_bscale[1];
    const float* bb = b1 + (long)(half * 16) * 16384 + h * 128 + w0;
    float* ob = out1 + (long)b * 524288 + (long)(half * 16) * 16384 + h * 128 + w0;
#pragma unroll
    for (int ip = 0; ip < 8; ip++) {
        float2 f0 = up2(acc[0][ip]), f1 = up2(acc[1][ip]), f2 = up2(acc[2][ip]), f3 = up2(acc[3][ip]);
        float4 bv0 = *reinterpret_cast<const float4*>(bb + (2 * ip) * 16384);
        float4 bv1 = *reinterpret_cast<const float4*>(bb + (2 * ip + 1) * 16384);
        *(float4*)(ob + (2 * ip) * 16384) =
            make_float4(fmaf(bs, bv0.x, f0.x), fmaf(bs, bv0.y, f1.x),
                        fmaf(bs, bv0.z, f2.x), fmaf(bs, bv0.w, f3.x));
        *(float4*)(ob + (2 * ip + 1) * 16384) =
            make_float4(fmaf(bs, bv1.x, f0.y), fmaf(bs, bv1.y, f1.y),
                        fmaf(bs, bv1.z, f2.y), fmaf(bs, bv1.w, f3.y));
    }
}

// ---------------- launch ----------------
extern "C" void kernel_launch(void* const* d_in, const int* in_sizes, int n_in,
                              void* d_out, int out_size) {
    const float* x0  = (const float*)d_in[0];
    const float* x1  = (const float*)d_in[1];
    const float* W00 = (const float*)d_in[2];
    const float* W10 = (const float*)d_in[3];
    const float* W11 = (const float*)d_in[4];
    const float* b0  = (const float*)d_in[5];
    const float* b1  = (const float*)d_in[6];
    const float* g   = (const float*)d_in[7];
    float* out0 = (float*)d_out;
    float* out1 = out0 + (long)16 * 16 * 256 * 256;

    k_ssq<<<192, 256>>>(b0, b1);
    k_prep<<<6, 256>>>(W00, W10, W11, g);
    k_y0<<<dim3(66, 1, 16), 256, 1152 * 8>>>(x0, W00);
    k_y1<<<dim3(17, 1, 32), 256, 3456 * 8>>>(x0, x1, W10, W11);
    k_z0<<<dim3(2, 32, 16), 256, 3968 * 8>>>(x0, W00, W10, b0, out0);
    k_z1<<<dim3(1, 16, 32), 256, 2432 * 8>>>(x1, W11, b1, out1);
}

// round 13
// speedup vs baseline: 1.1919x; 1.0992x over previous
#include <cuda_runtime.h>

// ---------------- scratch ----------------
__device__ __align__(16) float d_Y0[16 * 16 * 258 * 258];   // (B,16,258,258)
__device__ __align__(16) float d_Y1[16 * 32 * 130 * 130];   // (B,32,130,130)
__device__ float d_blk0[1024];   // [r2][c2][m16][n16]
__device__ float d_blk1[512];    // [g2][m16][n16]
__device__ float d_part[192];
__device__ float d_bscale[2];

typedef unsigned long long u64;

// ---------------- f32x2 helpers ----------------
__device__ __forceinline__ u64 pk2(float a, float b) {
    u64 r;
    asm("mov.b64 %0, {%1, %2};" : "=l"(r) : "r"(__float_as_uint(a)), "r"(__float_as_uint(b)));
    return r;
}
__device__ __forceinline__ u64 dup2(float a) { return pk2(a, a); }
__device__ __forceinline__ void dfma(u64& d, u64 a, u64 b) {
    asm("fma.rn.f32x2 %0, %1, %2, %0;" : "+l"(d) : "l"(a), "l"(b));
}
__device__ __forceinline__ float2 up2(u64 v) {
    unsigned lo, hi;
    asm("mov.b64 {%0, %1}, %2;" : "=r"(lo), "=r"(hi) : "l"(v));
    return make_float2(__uint_as_float(lo), __uint_as_float(hi));
}
__device__ __forceinline__ void ldw8(const u64* p, u64 wr[8]) {
    const ulonglong2* q = (const ulonglong2*)p;
    ulonglong2 a = q[0], b = q[1], c = q[2], d = q[3];
    wr[0] = a.x; wr[1] = a.y; wr[2] = b.x; wr[3] = b.y;
    wr[4] = c.x; wr[5] = c.y; wr[6] = d.x; wr[7] = d.y;
}

// ---------------- P1: partial sum of squares for b0,b1 ----------------
__global__ __launch_bounds__(256) void k_ssq(const float* __restrict__ b0,
                                             const float* __restrict__ b1) {
    __shared__ float red[256];
    int bid = blockIdx.x, t = threadIdx.x;
    const float* src; long base;
    if (bid < 128) { src = b0; base = (long)bid * 8192; }
    else           { src = b1; base = (long)(bid - 128) * 8192; }
    float s = 0.f;
#pragma unroll
    for (int k = 0; k < 32; k++) { float v = __ldg(src + base + k * 256 + t); s += v * v; }
    red[t] = s; __syncthreads();
    for (int off = 128; off; off >>= 1) { if (t < off) red[t] += red[t + off]; __syncthreads(); }
    if (t == 0) d_part[bid] = red[0];
}

// ---------------- P2 (parallel, 6 blocks): bscale + Gram matrices --------------
__global__ __launch_bounds__(256) void k_prep(const float* __restrict__ W00,
                                              const float* __restrict__ W10,
                                              const float* __restrict__ W11,
                                              const float* __restrict__ g) {
    __shared__ float sw[9216];
    int blk = blockIdx.x, t = threadIdx.x;
    if (blk == 0 && t == 0) {
        float s0 = 0.f, s1 = 0.f;
        for (int i = 0; i < 128; i++) s0 += d_part[i];
        for (int i = 128; i < 192; i++) s1 += d_part[i];
        d_bscale[0] = __ldg(g) * rsqrtf(s0);
        d_bscale[1] = __ldg(g + 1) * rsqrtf(s1);
    }
    if (blk < 4) {
        for (int i = t; i < 2304; i += 256) sw[i] = __ldg(W00 + i);
        for (int i = t; i < 4608; i += 256) sw[2304 + i] = __ldg(W10 + i);
        __syncthreads();
        const float* s0 = sw;
        const float* s1 = sw + 2304;
        int e = blk * 256 + t;
        int n = e & 15, m = (e >> 4) & 15, c = (e >> 8) & 1, r = (e >> 9) & 1;
        float acc = 0.f;
        for (int o = 0; o < 16; o++) {
            const float* pm = s0 + (o * 16 + m) * 9;
            const float* pn = s0 + (o * 16 + n) * 9;
#pragma unroll
            for (int ij = 0; ij < 9; ij++) acc += pm[ij] * pn[ij];
        }
#pragma unroll
        for (int i1 = 0; i1 < 3; i1++) {
            if (((i1 + 1) & 1) != r) continue;
#pragma unroll
            for (int j1 = 0; j1 < 3; j1++) {
                if (((j1 + 1) & 1) != c) continue;
                int ij = i1 * 3 + j1;
                for (int o = 0; o < 32; o++)
                    acc += s1[(o * 16 + m) * 9 + ij] * s1[(o * 16 + n) * 9 + ij];
            }
        }
        d_blk0[e] = acc;   // ((r*2+c)*16+m)*16+n
    } else {
        for (int i = t; i < 9216; i += 256) sw[i] = __ldg(W11 + i);
        __syncthreads();
        int e = (blk - 4) * 256 + t;   // [0,512)
        int n = e & 15, m = (e >> 4) & 15, gg = e >> 8;
        float acc = 0.f;
        for (int o = 0; o < 32; o++) {
            const float* pm = sw + (o * 32 + gg * 16 + m) * 9;
            const float* pn = sw + (o * 32 + gg * 16 + n) * 9;
#pragma unroll
            for (int ij = 0; ij < 9; ij++) acc += pm[ij] * pn[ij];
        }
        d_blk1[e] = acc;   // (gg*16+m)*16+n
    }
}

// ---------------- Y0 = conv(x0, W00, s1, p2); dy-outer + ic prefetch ----------
__global__ __launch_bounds__(256, 2) void k_y0(const float* __restrict__ x0,
                                               const float* __restrict__ W00) {
    extern __shared__ u64 sm[];   // 1152: [(ic*9+tap)*8+ip]
    int t = threadIdx.x;
    for (int idx = t; idx < 1152; idx += 256) {
        int ip = idx & 7, rest = idx >> 3, tap = rest % 9, ic = rest / 9;
        float wa = __ldg(W00 + ((2 * ip) * 16 + ic) * 9 + tap);
        float wb = __ldg(W00 + ((2 * ip + 1) * 16 + ic) * 9 + tap);
        sm[idx] = pk2(wa, wb);
    }
    __syncthreads();
    int b = blockIdx.z;
    int item = blockIdx.x * 256 + t;
    int r = item / 65, q = item - r * 65;
    int w0 = q * 4;
    bool valid = (r < 258);
    u64 acc[4][8];
#pragma unroll
    for (int p = 0; p < 4; p++)
#pragma unroll
        for (int ip = 0; ip < 8; ip++) acc[p][ip] = 0ull;
    const float* xb = x0 + (long)b * 1048576;
#pragma unroll 1
    for (int dy = 0; dy < 3; dy++) {
        int iy = r - 2 + dy;
        bool rowok = valid && iy >= 0 && iy < 256;
        const float* rowp = xb + iy * 256;
        float v[6];
#pragma unroll
        for (int j = 0; j < 6; j++) {
            int ix = w0 - 2 + j;
            v[j] = (rowok && ix >= 0 && ix < 256) ? __ldg(rowp + ix) : 0.f;
        }
#pragma unroll 1
        for (int ic = 0; ic < 16; ic++) {
            int icn = ic < 15 ? ic + 1 : ic;
            const float* nrow = xb + icn * 65536 + iy * 256;
            float nv[6];
#pragma unroll
            for (int j = 0; j < 6; j++) {
                int ix = w0 - 2 + j;
                nv[j] = (rowok && ix >= 0 && ix < 256) ? __ldg(nrow + ix) : 0.f;
            }
            const u64* wbase = sm + ic * 72 + dy * 24;
#pragma unroll
            for (int dx = 0; dx < 3; dx++) {
                u64 wr[8];
                ldw8(wbase + dx * 8, wr);
#pragma unroll
                for (int p = 0; p < 4; p++) {
                    u64 a = dup2(v[p + dx]);
#pragma unroll
                    for (int ip = 0; ip < 8; ip++) dfma(acc[p][ip], wr[ip], a);
                }
            }
#pragma unroll
            for (int j = 0; j < 6; j++) v[j] = nv[j];
        }
    }
    if (valid) {
        float* yb = d_Y0 + (long)b * 1065024 + r * 258 + w0;
        if (w0 + 4 <= 258) {
#pragma unroll
            for (int ip = 0; ip < 8; ip++) {
                float2 f0 = up2(acc[0][ip]), f1 = up2(acc[1][ip]), f2 = up2(acc[2][ip]), f3 = up2(acc[3][ip]);
                yb[(2 * ip) * 66564 + 0] = f0.x; yb[(2 * ip) * 66564 + 1] = f1.x;
                yb[(2 * ip) * 66564 + 2] = f2.x; yb[(2 * ip) * 66564 + 3] = f3.x;
                yb[(2 * ip + 1) * 66564 + 0] = f0.y; yb[(2 * ip + 1) * 66564 + 1] = f1.y;
                yb[(2 * ip + 1) * 66564 + 2] = f2.y; yb[(2 * ip + 1) * 66564 + 3] = f3.y;
            }
        } else {
#pragma unroll
            for (int p = 0; p < 4; p++) {
                if (w0 + p >= 258) break;
#pragma unroll
                for (int ip = 0; ip < 8; ip++) {
                    float2 f = up2(acc[p][ip]);
                    yb[(2 * ip) * 66564 + p] = f.x;
                    yb[(2 * ip + 1) * 66564 + p] = f.y;
                }
            }
        }
    }
}

// ------- Y1 = conv(x0,W10,s2,p3) + conv(x1,W11,s1,p2); ic prefetch ------------
__global__ __launch_bounds__(256, 2) void k_y1(const float* __restrict__ x0,
                                               const float* __restrict__ x1,
                                               const float* __restrict__ W10,
                                               const float* __restrict__ W11) {
    extern __shared__ u64 sm[];   // sA 1152 + sB 2304
    u64* sA = sm; u64* sB2 = sm + 1152;
    int t = threadIdx.x;
    int half = blockIdx.z & 1, b = blockIdx.z >> 1;
    for (int idx = t; idx < 1152; idx += 256) {
        int ip = idx & 7, rest = idx >> 3, tap = rest % 9, ic = rest / 9;
        float wa = __ldg(W10 + ((half * 16 + 2 * ip) * 16 + ic) * 9 + tap);
        float wb = __ldg(W10 + ((half * 16 + 2 * ip + 1) * 16 + ic) * 9 + tap);
        sA[idx] = pk2(wa, wb);
    }
    for (int idx = t; idx < 2304; idx += 256) {
        int ip = idx & 7, rest = idx >> 3, tap = rest % 9, ic = rest / 9;
        float wa = __ldg(W11 + ((half * 16 + 2 * ip) * 32 + ic) * 9 + tap);
        float wb = __ldg(W11 + ((half * 16 + 2 * ip + 1) * 32 + ic) * 9 + tap);
        sB2[idx] = pk2(wa, wb);
    }
    __syncthreads();
    int item = blockIdx.x * 256 + t;
    int u = item / 33, q = item - u * 33;
    int v0 = q * 4;
    bool valid = (u < 130);
    u64 acc[4][8];
#pragma unroll
    for (int p = 0; p < 4; p++)
#pragma unroll
        for (int ip = 0; ip < 8; ip++) acc[p][ip] = 0ull;
    // phase A: stride-2 over x0; dy-outer, ic-inner with prefetch
    const float* xa = x0 + (long)b * 1048576;
#pragma unroll 1
    for (int dy = 0; dy < 3; dy++) {
        int iy = 2 * u - 3 + dy;
        bool rowok = valid && iy >= 0 && iy < 256;
        const float* rowp = xa + iy * 256;
        float v[9];
#pragma unroll
        for (int j = 0; j < 9; j++) {
            int ix = 2 * v0 - 3 + j;
            v[j] = (rowok && ix >= 0 && ix < 256) ? __ldg(rowp + ix) : 0.f;
        }
#pragma unroll 1
        for (int ic = 0; ic < 16; ic++) {
            int icn = ic < 15 ? ic + 1 : ic;
            const float* nrow = xa + icn * 65536 + iy * 256;
            float nv[9];
#pragma unroll
            for (int j = 0; j < 9; j++) {
                int ix = 2 * v0 - 3 + j;
                nv[j] = (rowok && ix >= 0 && ix < 256) ? __ldg(nrow + ix) : 0.f;
            }
            const u64* wbase = sA + ic * 72 + dy * 24;
#pragma unroll
            for (int dx = 0; dx < 3; dx++) {
                u64 wr[8];
                ldw8(wbase + dx * 8, wr);
#pragma unroll
                for (int p = 0; p < 4; p++) {
                    u64 a = dup2(v[2 * p + dx]);
#pragma unroll
                    for (int ip = 0; ip < 8; ip++) dfma(acc[p][ip], wr[ip], a);
                }
            }
#pragma unroll
            for (int j = 0; j < 9; j++) v[j] = nv[j];
        }
    }
    // phase B: stride-1 over x1
    const float* xb1 = x1 + (long)b * 524288;
#pragma unroll 1
    for (int dy = 0; dy < 3; dy++) {
        int iy = u - 2 + dy;
        bool rowok = valid && iy >= 0 && iy < 128;
        const float* rowp = xb1 + iy * 128;
        float v[6];
#pragma unroll
        for (int j = 0; j < 6; j++) {
            int ix = v0 - 2 + j;
            v[j] = (rowok && ix >= 0 && ix < 128) ? __ldg(rowp + ix) : 0.f;
        }
#pragma unroll 1
        for (int ic = 0; ic < 32; ic++) {
            int icn = ic < 31 ? ic + 1 : ic;
            const float* nrow = xb1 + icn * 16384 + iy * 128;
            float nv[6];
#pragma unroll
            for (int j = 0; j < 6; j++) {
                int ix = v0 - 2 + j;
                nv[j] = (rowok && ix >= 0 && ix < 128) ? __ldg(nrow + ix) : 0.f;
            }
            const u64* wbase = sB2 + ic * 72 + dy * 24;
#pragma unroll
            for (int dx = 0; dx < 3; dx++) {
                u64 wr[8];
                ldw8(wbase + dx * 8, wr);
#pragma unroll
                for (int p = 0; p < 4; p++) {
                    u64 a = dup2(v[p + dx]);
#pragma unroll
                    for (int ip = 0; ip < 8; ip++) dfma(acc[p][ip], wr[ip], a);
                }
            }
#pragma unroll
            for (int j = 0; j < 6; j++) v[j] = nv[j];
        }
    }
    if (valid) {
        float* yb = d_Y1 + (long)b * 540800 + (long)(half * 16) * 16900 + u * 130 + v0;
#pragma unroll
        for (int p = 0; p < 4; p++) {
            if (v0 + p >= 130) break;
#pragma unroll
            for (int ip = 0; ip < 8; ip++) {
                float2 f = up2(acc[p][ip]);
                yb[(2 * ip) * 16900 + p] = f.x;
                yb[(2 * ip + 1) * 16900 + p] = f.y;
            }
        }
    }
}

// ---- Z0: out0 = -convt(Y0,W00,s1,p2) - convt(Y1,W10,s2,p3,op1) + diag + bias --
__global__ __launch_bounds__(256, 2) void k_z0(const float* __restrict__ x0,
                                               const float* __restrict__ W00,
                                               const float* __restrict__ W10,
                                               const float* __restrict__ b0,
                                               float* __restrict__ out) {
    extern __shared__ u64 sm[];   // sW 1152 | sBk 512 | sT 2304
    u64* sW = sm; u64* sBk = sm + 1152; u64* sT = sm + 1664;
    int t = threadIdx.x;
    for (int idx = t; idx < 1152; idx += 256) {
        int ip = idx & 7, rest = idx >> 3, tap = rest % 9, o = rest / 9;
        float wa = -__ldg(W00 + (o * 16 + 2 * ip) * 9 + tap);
        float wb = -__ldg(W00 + (o * 16 + 2 * ip + 1) * 9 + tap);
        sW[idx] = pk2(wa, wb);
    }
    for (int idx = t; idx < 512; idx += 256) {
        int ip = idx & 7, n = (idx >> 3) & 15, rc = idx >> 7;
        float a0 = d_blk0[(rc * 16 + 2 * ip) * 16 + n];
        float a1 = d_blk0[(rc * 16 + 2 * ip + 1) * 16 + n];
        sBk[idx] = pk2(a0, a1);
    }
    for (int idx = t; idx < 2304; idx += 256) {
        int ip = idx & 7, rest = idx >> 3, o = rest & 31, tap = rest >> 5;
        float wa = -__ldg(W10 + (o * 16 + 2 * ip) * 9 + tap);
        float wb = -__ldg(W10 + (o * 16 + 2 * ip + 1) * 9 + tap);
        sT[idx] = pk2(wa, wb);
    }
    __syncthreads();
    int b = blockIdx.z, lane = t & 31, warp = t >> 5;
    int h = blockIdx.y * 8 + warp;
    int w0 = (blockIdx.x * 32 + lane) * 4;
    u64 acc[4][8];
#pragma unroll
    for (int p = 0; p < 4; p++)
#pragma unroll
        for (int ip = 0; ip < 8; ip++) acc[p][ip] = 0ull;

    // term1: -convt(Y0,W00)
    const float* yb = d_Y0 + (long)b * 1065024 + h * 258 + w0;
#pragma unroll 1
    for (int o = 0; o < 16; o++) {
        const float* yc = yb + o * 66564;
        float yv[3][6];
#pragma unroll
        for (int rr = 0; rr < 3; rr++) {
            float2 a = *reinterpret_cast<const float2*>(yc + rr * 258);
            float2 c = *reinterpret_cast<const float2*>(yc + rr * 258 + 2);
            float2 e = *reinterpret_cast<const float2*>(yc + rr * 258 + 4);
            yv[rr][0] = a.x; yv[rr][1] = a.y; yv[rr][2] = c.x;
            yv[rr][3] = c.y; yv[rr][4] = e.x; yv[rr][5] = e.y;
        }
        const u64* wbase = sW + o * 72;
#pragma unroll
        for (int dy = 0; dy < 3; dy++)
#pragma unroll
            for (int dx = 0; dx < 3; dx++) {
                const u64* wp = wbase + (dy * 3 + dx) * 8;
                u64 wr[8];
#pragma unroll
                for (int ip = 0; ip < 8; ip++) wr[ip] = wp[ip];
#pragma unroll
                for (int p = 0; p < 4; p++) {
                    u64 a = dup2(yv[2 - dy][p + 2 - dx]);
#pragma unroll
                    for (int ip = 0; ip < 8; ip++) dfma(acc[p][ip], wr[ip], a);
                }
            }
    }
    // term2: -convt(Y1,W10,s2,p3,op1)
    {
        int qc = (w0 >> 1) + 1;
        int hp = h & 1;
        int ntap = hp ? 2 : 1;
        int dy0 = hp ? 0 : 1;
        int qr0 = hp ? ((h + 3) >> 1) : ((h >> 1) + 1);
        int qr1 = (h + 1) >> 1;
        const float* y1b = d_Y1 + (long)b * 540800;
#pragma unroll 1
        for (int o = 0; o < 32; o++) {
            const float* yo = y1b + o * 16900;
            for (int tt = 0; tt < ntap; tt++) {
                int dy = tt ? 2 : dy0;
                int qr = tt ? qr1 : qr0;
                const float* yr = yo + qr * 130 + qc;
                float yA = __ldg(yr), yB = __ldg(yr + 1), yC = __ldg(yr + 2);
                u64 aA = dup2(yA), aB = dup2(yB), aC = dup2(yC);
                const u64* w0p = sT + ((dy * 3 + 0) * 32 + o) * 8;
                const u64* w1p = sT + ((dy * 3 + 1) * 32 + o) * 8;
                const u64* w2p = sT + ((dy * 3 + 2) * 32 + o) * 8;
#pragma unroll
                for (int ip = 0; ip < 8; ip++) {
                    u64 r0v = w0p[ip], r1v = w1p[ip], r2v = w2p[ip];
                    dfma(acc[0][ip], r1v, aA);
                    dfma(acc[1][ip], r0v, aB);
                    dfma(acc[1][ip], r2v, aA);
                    dfma(acc[2][ip], r1v, aB);
                    dfma(acc[3][ip], r0v, aC);
                    dfma(acc[3][ip], r2v, aB);
                }
            }
        }
    }
    // term3: +diag
    {
        int r = h & 1;
        const u64* sb0 = sBk + (r * 2 + 0) * 128;
        const u64* sb1 = sBk + (r * 2 + 1) * 128;
        const float* xq = x0 + (long)b * 1048576 + h * 256 + w0;
#pragma unroll 1
        for (int n = 0; n < 16; n++) {
            float4 xv = *reinterpret_cast<const float4*>(xq + n * 65536);
            u64 a0 = dup2(xv.x), a1 = dup2(xv.y), a2 = dup2(xv.z), a3 = dup2(xv.w);
            const u64* b0p = sb0 + n * 8;
            const u64* b1p = sb1 + n * 8;
#pragma unroll
            for (int ip = 0; ip < 8; ip++) {
                u64 e = b0p[ip], od = b1p[ip];
                dfma(acc[0][ip], e, a0);
                dfma(acc[1][ip], od, a1);
                dfma(acc[2][ip], e, a2);
                dfma(acc[3][ip], od, a3);
            }
        }
    }
    float bs = d_bscale[0];
    const float* bb = b0 + h * 256 + w0;
    float* ob = out + (long)b * 1048576 + h * 256 + w0;
#pragma unroll
    for (int ip = 0; ip < 8; ip++) {
        float2 f0 = up2(acc[0][ip]), f1 = up2(acc[1][ip]), f2 = up2(acc[2][ip]), f3 = up2(acc[3][ip]);
        float4 bv0 = *reinterpret_cast<const float4*>(bb + (2 * ip) * 65536);
        float4 bv1 = *reinterpret_cast<const float4*>(bb + (2 * ip + 1) * 65536);
        *(float4*)(ob + (2 * ip) * 65536) =
            make_float4(fmaf(bs, bv0.x, f0.x), fmaf(bs, bv0.y, f1.x),
                        fmaf(bs, bv0.z, f2.x), fmaf(bs, bv0.w, f3.x));
        *(float4*)(ob + (2 * ip + 1) * 65536) =
            make_float4(fmaf(bs, bv1.x, f0.y), fmaf(bs, bv1.y, f1.y),
                        fmaf(bs, bv1.z, f2.y), fmaf(bs, bv1.w, f3.y));
    }
}

// -------- Z1: out1 = -convt(Y1,W11,s1,p2) + diag(blk1,x1) + bias ---------------
__global__ __launch_bounds__(256, 2) void k_z1(const float* __restrict__ x1,
                                               const float* __restrict__ W11,
                                               const float* __restrict__ b1,
                                               float* __restrict__ out1) {
    extern __shared__ u64 sm[];   // sW 2304 + sB 128
    u64* sW = sm; u64* sB = sm + 2304;
    int t = threadIdx.x;
    int half = blockIdx.z & 1, b = blockIdx.z >> 1;
    for (int idx = t; idx < 2304; idx += 256) {
        int ip = idx & 7, rest = idx >> 3, tap = rest % 9, o = rest / 9;
        float wa = -__ldg(W11 + (o * 32 + half * 16 + 2 * ip) * 9 + tap);
        float wb = -__ldg(W11 + (o * 32 + half * 16 + 2 * ip + 1) * 9 + tap);
        sW[idx] = pk2(wa, wb);
    }
    for (int idx = t; idx < 128; idx += 256) {
        int ip = idx & 7, n = idx >> 3;
        float a0 = d_blk1[half * 256 + (2 * ip) * 16 + n];
        float a1 = d_blk1[half * 256 + (2 * ip + 1) * 16 + n];
        sB[idx] = pk2(a0, a1);
    }
    __syncthreads();
    int lane = t & 31, warp = t >> 5;
    int h = blockIdx.y * 8 + warp;
    int w0 = lane * 4;
    u64 acc[4][8];
#pragma unroll
    for (int p = 0; p < 4; p++)
#pragma unroll
        for (int ip = 0; ip < 8; ip++) acc[p][ip] = 0ull;
    const float* yb = d_Y1 + (long)b * 540800 + h * 130 + w0;
#pragma unroll 1
    for (int o = 0; o < 32; o++) {
        const float* yc = yb + o * 16900;
        float yv[3][6];
#pragma unroll
        for (int rr = 0; rr < 3; rr++) {
            float2 a = *reinterpret_cast<const float2*>(yc + rr * 130);
            float2 c = *reinterpret_cast<const float2*>(yc + rr * 130 + 2);
            float2 e = *reinterpret_cast<const float2*>(yc + rr * 130 + 4);
            yv[rr][0] = a.x; yv[rr][1] = a.y; yv[rr][2] = c.x;
            yv[rr][3] = c.y; yv[rr][4] = e.x; yv[rr][5] = e.y;
        }
        const u64* wbase = sW + o * 72;
#pragma unroll
        for (int dy = 0; dy < 3; dy++)
#pragma unroll
            for (int dx = 0; dx < 3; dx++) {
                const u64* wp = wbase + (dy * 3 + dx) * 8;
                u64 wr[8];
#pragma unroll
                for (int ip = 0; ip < 8; ip++) wr[ip] = wp[ip];
#pragma unroll
                for (int p = 0; p < 4; p++) {
                    u64 a = dup2(yv[2 - dy][p + 2 - dx]);
#pragma unroll
                    for (int ip = 0; ip < 8; ip++) dfma(acc[p][ip], wr[ip], a);
                }
            }
    }
    // diag
    {
        const float* xq = x1 + (long)b * 524288 + (long)(half * 16) * 16384 + h * 128 + w0;
#pragma unroll 1
        for (int n = 0; n < 16; n++) {
            float4 xv = *reinterpret_cast<const float4*>(xq + n * 16384);
            u64 a0 = dup2(xv.x), a1 = dup2(xv.y), a2 = dup2(xv.z), a3 = dup2(xv.w);
            const u64* bp = sB + n * 8;
#pragma unroll
            for (int ip = 0; ip < 8; ip++) {
                u64 e = bp[ip];
                dfma(acc[0][ip], e, a0);
                dfma(acc[1][ip], e, a1);
                dfma(acc[2][ip], e, a2);
                dfma(acc[3][ip], e, a3);
            }
        }
    }
    float bs = d_bscale[1];
    const float* bb = b1 + (long)(half * 16) * 16384 + h * 128 + w0;
    float* ob = out1 + (long)b * 524288 + (long)(half * 16) * 16384 + h * 128 + w0;
#pragma unroll
    for (int ip = 0; ip < 8; ip++) {
        float2 f0 = up2(acc[0][ip]), f1 = up2(acc[1][ip]), f2 = up2(acc[2][ip]), f3 = up2(acc[3][ip]);
        float4 bv0 = *reinterpret_cast<const float4*>(bb + (2 * ip) * 16384);
        float4 bv1 = *reinterpret_cast<const float4*>(bb + (2 * ip + 1) * 16384);
        *(float4*)(ob + (2 * ip) * 16384) =
            make_float4(fmaf(bs, bv0.x, f0.x), fmaf(bs, bv0.y, f1.x),
                        fmaf(bs, bv0.z, f2.x), fmaf(bs, bv0.w, f3.x));
        *(float4*)(ob + (2 * ip + 1) * 16384) =
            make_float4(fmaf(bs, bv1.x, f0.y), fmaf(bs, bv1.y, f1.y),
                        fmaf(bs, bv1.z, f2.y), fmaf(bs, bv1.w, f3.y));
    }
}

// ---------------- launch: multi-stream fork-join DAG ----------------
extern "C" void kernel_launch(void* const* d_in, const int* in_sizes, int n_in,
                              void* d_out, int out_size) {
    const float* x0  = (const float*)d_in[0];
    const float* x1  = (const float*)d_in[1];
    const float* W00 = (const float*)d_in[2];
    const float* W10 = (const float*)d_in[3];
    const float* W11 = (const float*)d_in[4];
    const float* b0  = (const float*)d_in[5];
    const float* b1  = (const float*)d_in[6];
    const float* g   = (const float*)d_in[7];
    float* out0 = (float*)d_out;
    float* out1 = out0 + (long)16 * 16 * 256 * 256;

    // Side streams/events: created once on the first call (the correctness run,
    // outside graph capture). They carry no state that affects the computed
    // work — the DAG is identical on every call.
    static cudaStream_t sPrep = nullptr, sY1 = nullptr;
    static cudaEvent_t eFork = nullptr, ePrep = nullptr, eY1 = nullptr, eZ1 = nullptr;
    if (sPrep == nullptr) {
        cudaStreamCreateWithFlags(&sPrep, cudaStreamNonBlocking);
        cudaStreamCreateWithFlags(&sY1, cudaStreamNonBlocking);
        cudaEventCreateWithFlags(&eFork, cudaEventDisableTiming);
        cudaEventCreateWithFlags(&ePrep, cudaEventDisableTiming);
        cudaEventCreateWithFlags(&eY1, cudaEventDisableTiming);
        cudaEventCreateWithFlags(&eZ1, cudaEventDisableTiming);
    }

    // fork from the origin (legacy default) stream
    cudaEventRecord(eFork, 0);
    cudaStreamWaitEvent(sPrep, eFork, 0);
    cudaStreamWaitEvent(sY1, eFork, 0);

    // branch A (sPrep): bias norms + Gram matrices
    k_ssq<<<192, 256, 0, sPrep>>>(b0, b1);
    k_prep<<<6, 256, 0, sPrep>>>(W00, W10, W11, g);
    cudaEventRecord(ePrep, sPrep);

    // branch B (sY1): Y1 (long pole), then Z1 (needs Y1 + prep only)
    k_y1<<<dim3(17, 1, 32), 256, 3456 * 8, sY1>>>(x0, x1, W10, W11);
    cudaEventRecord(eY1, sY1);
    cudaStreamWaitEvent(sY1, ePrep, 0);
    k_z1<<<dim3(1, 16, 32), 256, 2432 * 8, sY1>>>(x1, W11, b1, out1);
    cudaEventRecord(eZ1, sY1);

    // branch C (origin): Y0, then Z0 (needs Y0 + Y1 + prep)
    k_y0<<<dim3(66, 1, 16), 256, 1152 * 8>>>(x0, W00);
    cudaStreamWaitEvent(0, eY1, 0);
    cudaStreamWaitEvent(0, ePrep, 0);
    k_z0<<<dim3(2, 32, 16), 256, 3968 * 8>>>(x0, W00, W10, b0, out0);

    // join
    cudaStreamWaitEvent(0, eZ1, 0);
}

// round 14
// speedup vs baseline: 1.2294x; 1.0314x over previous
#include <cuda_runtime.h>

// ---------------- scratch ----------------
__device__ __align__(16) float d_Y0[16 * 16 * 258 * 258];   // (B,16,258,258)
__device__ __align__(16) float d_Y1[16 * 32 * 130 * 130];   // (B,32,130,130)
__device__ float d_blk0[1024];   // [r2][c2][m16][n16]
__device__ float d_blk1[512];    // [g2][m16][n16]
__device__ float d_part[192];
__device__ float d_bscale[2];

typedef unsigned long long u64;

// ---------------- f32x2 helpers ----------------
__device__ __forceinline__ u64 pk2(float a, float b) {
    u64 r;
    asm("mov.b64 %0, {%1, %2};" : "=l"(r) : "r"(__float_as_uint(a)), "r"(__float_as_uint(b)));
    return r;
}
__device__ __forceinline__ u64 dup2(float a) { return pk2(a, a); }
__device__ __forceinline__ void dfma(u64& d, u64 a, u64 b) {
    asm("fma.rn.f32x2 %0, %1, %2, %0;" : "+l"(d) : "l"(a), "l"(b));
}
__device__ __forceinline__ float2 up2(u64 v) {
    unsigned lo, hi;
    asm("mov.b64 {%0, %1}, %2;" : "=r"(lo), "=r"(hi) : "l"(v));
    return make_float2(__uint_as_float(lo), __uint_as_float(hi));
}
__device__ __forceinline__ void ldw8(const u64* p, u64 wr[8]) {
    const ulonglong2* q = (const ulonglong2*)p;
    ulonglong2 a = q[0], b = q[1], c = q[2], d = q[3];
    wr[0] = a.x; wr[1] = a.y; wr[2] = b.x; wr[3] = b.y;
    wr[4] = c.x; wr[5] = c.y; wr[6] = d.x; wr[7] = d.y;
}

// ---------------- P1: partial sum of squares for b0,b1 ----------------
__global__ __launch_bounds__(256) void k_ssq(const float* __restrict__ b0,
                                             const float* __restrict__ b1) {
    __shared__ float red[256];
    int bid = blockIdx.x, t = threadIdx.x;
    const float* src; long base;
    if (bid < 128) { src = b0; base = (long)bid * 8192; }
    else           { src = b1; base = (long)(bid - 128) * 8192; }
    float s = 0.f;
#pragma unroll
    for (int k = 0; k < 32; k++) { float v = __ldg(src + base + k * 256 + t); s += v * v; }
    red[t] = s; __syncthreads();
    for (int off = 128; off; off >>= 1) { if (t < off) red[t] += red[t + off]; __syncthreads(); }
    if (t == 0) d_part[bid] = red[0];
}

// ---------------- P2 (parallel, 6 blocks): bscale + Gram matrices --------------
__global__ __launch_bounds__(256) void k_prep(const float* __restrict__ W00,
                                              const float* __restrict__ W10,
                                              const float* __restrict__ W11,
                                              const float* __restrict__ g) {
    __shared__ float sw[9216];
    int blk = blockIdx.x, t = threadIdx.x;
    if (blk == 0 && t == 0) {
        float s0 = 0.f, s1 = 0.f;
        for (int i = 0; i < 128; i++) s0 += d_part[i];
        for (int i = 128; i < 192; i++) s1 += d_part[i];
        d_bscale[0] = __ldg(g) * rsqrtf(s0);
        d_bscale[1] = __ldg(g + 1) * rsqrtf(s1);
    }
    if (blk < 4) {
        for (int i = t; i < 2304; i += 256) sw[i] = __ldg(W00 + i);
        for (int i = t; i < 4608; i += 256) sw[2304 + i] = __ldg(W10 + i);
        __syncthreads();
        const float* s0 = sw;
        const float* s1 = sw + 2304;
        int e = blk * 256 + t;
        int n = e & 15, m = (e >> 4) & 15, c = (e >> 8) & 1, r = (e >> 9) & 1;
        float acc = 0.f;
        for (int o = 0; o < 16; o++) {
            const float* pm = s0 + (o * 16 + m) * 9;
            const float* pn = s0 + (o * 16 + n) * 9;
#pragma unroll
            for (int ij = 0; ij < 9; ij++) acc += pm[ij] * pn[ij];
        }
#pragma unroll
        for (int i1 = 0; i1 < 3; i1++) {
            if (((i1 + 1) & 1) != r) continue;
#pragma unroll
            for (int j1 = 0; j1 < 3; j1++) {
                if (((j1 + 1) & 1) != c) continue;
                int ij = i1 * 3 + j1;
                for (int o = 0; o < 32; o++)
                    acc += s1[(o * 16 + m) * 9 + ij] * s1[(o * 16 + n) * 9 + ij];
            }
        }
        d_blk0[e] = acc;
    } else {
        for (int i = t; i < 9216; i += 256) sw[i] = __ldg(W11 + i);
        __syncthreads();
        int e = (blk - 4) * 256 + t;
        int n = e & 15, m = (e >> 4) & 15, gg = e >> 8;
        float acc = 0.f;
        for (int o = 0; o < 32; o++) {
            const float* pm = sw + (o * 32 + gg * 16 + m) * 9;
            const float* pn = sw + (o * 32 + gg * 16 + n) * 9;
#pragma unroll
            for (int ij = 0; ij < 9; ij++) acc += pm[ij] * pn[ij];
        }
        d_blk1[e] = acc;
    }
}

// ---------------- Y0 = conv(x0, W00, s1, p2); dy-outer + ic prefetch ----------
__global__ __launch_bounds__(256, 2) void k_y0(const float* __restrict__ x0,
                                               const float* __restrict__ W00,
                                               int bbase) {
    extern __shared__ u64 sm[];
    int t = threadIdx.x;
    for (int idx = t; idx < 1152; idx += 256) {
        int ip = idx & 7, rest = idx >> 3, tap = rest % 9, ic = rest / 9;
        float wa = __ldg(W00 + ((2 * ip) * 16 + ic) * 9 + tap);
        float wb = __ldg(W00 + ((2 * ip + 1) * 16 + ic) * 9 + tap);
        sm[idx] = pk2(wa, wb);
    }
    __syncthreads();
    int b = bbase + blockIdx.z;
    int item = blockIdx.x * 256 + t;
    int r = item / 65, q = item - r * 65;
    int w0 = q * 4;
    bool valid = (r < 258);
    u64 acc[4][8];
#pragma unroll
    for (int p = 0; p < 4; p++)
#pragma unroll
        for (int ip = 0; ip < 8; ip++) acc[p][ip] = 0ull;
    const float* xb = x0 + (long)b * 1048576;
#pragma unroll 1
    for (int dy = 0; dy < 3; dy++) {
        int iy = r - 2 + dy;
        bool rowok = valid && iy >= 0 && iy < 256;
        const float* rowp = xb + iy * 256;
        float v[6];
#pragma unroll
        for (int j = 0; j < 6; j++) {
            int ix = w0 - 2 + j;
            v[j] = (rowok && ix >= 0 && ix < 256) ? __ldg(rowp + ix) : 0.f;
        }
#pragma unroll 1
        for (int ic = 0; ic < 16; ic++) {
            int icn = ic < 15 ? ic + 1 : ic;
            const float* nrow = xb + icn * 65536 + iy * 256;
            float nv[6];
#pragma unroll
            for (int j = 0; j < 6; j++) {
                int ix = w0 - 2 + j;
                nv[j] = (rowok && ix >= 0 && ix < 256) ? __ldg(nrow + ix) : 0.f;
            }
            const u64* wbase = sm + ic * 72 + dy * 24;
#pragma unroll
            for (int dx = 0; dx < 3; dx++) {
                u64 wr[8];
                ldw8(wbase + dx * 8, wr);
#pragma unroll
                for (int p = 0; p < 4; p++) {
                    u64 a = dup2(v[p + dx]);
#pragma unroll
                    for (int ip = 0; ip < 8; ip++) dfma(acc[p][ip], wr[ip], a);
                }
            }
#pragma unroll
            for (int j = 0; j < 6; j++) v[j] = nv[j];
        }
    }
    if (valid) {
        float* yb = d_Y0 + (long)b * 1065024 + r * 258 + w0;
        if (w0 + 4 <= 258) {
#pragma unroll
            for (int ip = 0; ip < 8; ip++) {
                float2 f0 = up2(acc[0][ip]), f1 = up2(acc[1][ip]), f2 = up2(acc[2][ip]), f3 = up2(acc[3][ip]);
                yb[(2 * ip) * 66564 + 0] = f0.x; yb[(2 * ip) * 66564 + 1] = f1.x;
                yb[(2 * ip) * 66564 + 2] = f2.x; yb[(2 * ip) * 66564 + 3] = f3.x;
                yb[(2 * ip + 1) * 66564 + 0] = f0.y; yb[(2 * ip + 1) * 66564 + 1] = f1.y;
                yb[(2 * ip + 1) * 66564 + 2] = f2.y; yb[(2 * ip + 1) * 66564 + 3] = f3.y;
            }
        } else {
#pragma unroll
            for (int p = 0; p < 4; p++) {
                if (w0 + p >= 258) break;
#pragma unroll
                for (int ip = 0; ip < 8; ip++) {
                    float2 f = up2(acc[p][ip]);
                    yb[(2 * ip) * 66564 + p] = f.x;
                    yb[(2 * ip + 1) * 66564 + p] = f.y;
                }
            }
        }
    }
}

// ------- Y1 = conv(x0,W10,s2,p3) + conv(x1,W11,s1,p2); ic prefetch ------------
__global__ __launch_bounds__(256, 2) void k_y1(const float* __restrict__ x0,
                                               const float* __restrict__ x1,
                                               const float* __restrict__ W10,
                                               const float* __restrict__ W11,
                                               int bbase) {
    extern __shared__ u64 sm[];
    u64* sA = sm; u64* sB2 = sm + 1152;
    int t = threadIdx.x;
    int half = blockIdx.z & 1, b = bbase + (blockIdx.z >> 1);
    for (int idx = t; idx < 1152; idx += 256) {
        int ip = idx & 7, rest = idx >> 3, tap = rest % 9, ic = rest / 9;
        float wa = __ldg(W10 + ((half * 16 + 2 * ip) * 16 + ic) * 9 + tap);
        float wb = __ldg(W10 + ((half * 16 + 2 * ip + 1) * 16 + ic) * 9 + tap);
        sA[idx] = pk2(wa, wb);
    }
    for (int idx = t; idx < 2304; idx += 256) {
        int ip = idx & 7, rest = idx >> 3, tap = rest % 9, ic = rest / 9;
        float wa = __ldg(W11 + ((half * 16 + 2 * ip) * 32 + ic) * 9 + tap);
        float wb = __ldg(W11 + ((half * 16 + 2 * ip + 1) * 32 + ic) * 9 + tap);
        sB2[idx] = pk2(wa, wb);
    }
    __syncthreads();
    int item = blockIdx.x * 256 + t;
    int u = item / 33, q = item - u * 33;
    int v0 = q * 4;
    bool valid = (u < 130);
    u64 acc[4][8];
#pragma unroll
    for (int p = 0; p < 4; p++)
#pragma unroll
        for (int ip = 0; ip < 8; ip++) acc[p][ip] = 0ull;
    const float* xa = x0 + (long)b * 1048576;
#pragma unroll 1
    for (int dy = 0; dy < 3; dy++) {
        int iy = 2 * u - 3 + dy;
        bool rowok = valid && iy >= 0 && iy < 256;
        const float* rowp = xa + iy * 256;
        float v[9];
#pragma unroll
        for (int j = 0; j < 9; j++) {
            int ix = 2 * v0 - 3 + j;
            v[j] = (rowok && ix >= 0 && ix < 256) ? __ldg(rowp + ix) : 0.f;
        }
#pragma unroll 1
        for (int ic = 0; ic < 16; ic++) {
            int icn = ic < 15 ? ic + 1 : ic;
            const float* nrow = xa + icn * 65536 + iy * 256;
            float nv[9];
#pragma unroll
            for (int j = 0; j < 9; j++) {
                int ix = 2 * v0 - 3 + j;
                nv[j] = (rowok && ix >= 0 && ix < 256) ? __ldg(nrow + ix) : 0.f;
            }
            const u64* wbase = sA + ic * 72 + dy * 24;
#pragma unroll
            for (int dx = 0; dx < 3; dx++) {
                u64 wr[8];
                ldw8(wbase + dx * 8, wr);
#pragma unroll
                for (int p = 0; p < 4; p++) {
                    u64 a = dup2(v[2 * p + dx]);
#pragma unroll
                    for (int ip = 0; ip < 8; ip++) dfma(acc[p][ip], wr[ip], a);
                }
            }
#pragma unroll
            for (int j = 0; j < 9; j++) v[j] = nv[j];
        }
    }
    const float* xb1 = x1 + (long)b * 524288;
#pragma unroll 1
    for (int dy = 0; dy < 3; dy++) {
        int iy = u - 2 + dy;
        bool rowok = valid && iy >= 0 && iy < 128;
        const float* rowp = xb1 + iy * 128;
        float v[6];
#pragma unroll
        for (int j = 0; j < 6; j++) {
            int ix = v0 - 2 + j;
            v[j] = (rowok && ix >= 0 && ix < 128) ? __ldg(rowp + ix) : 0.f;
        }
#pragma unroll 1
        for (int ic = 0; ic < 32; ic++) {
            int icn = ic < 31 ? ic + 1 : ic;
            const float* nrow = xb1 + icn * 16384 + iy * 128;
            float nv[6];
#pragma unroll
            for (int j = 0; j < 6; j++) {
                int ix = v0 - 2 + j;
                nv[j] = (rowok && ix >= 0 && ix < 128) ? __ldg(nrow + ix) : 0.f;
            }
            const u64* wbase = sB2 + ic * 72 + dy * 24;
#pragma unroll
            for (int dx = 0; dx < 3; dx++) {
                u64 wr[8];
                ldw8(wbase + dx * 8, wr);
#pragma unroll
                for (int p = 0; p < 4; p++) {
                    u64 a = dup2(v[p + dx]);
#pragma unroll
                    for (int ip = 0; ip < 8; ip++) dfma(acc[p][ip], wr[ip], a);
                }
            }
#pragma unroll
            for (int j = 0; j < 6; j++) v[j] = nv[j];
        }
    }
    if (valid) {
        float* yb = d_Y1 + (long)b * 540800 + (long)(half * 16) * 16900 + u * 130 + v0;
#pragma unroll
        for (int p = 0; p < 4; p++) {
            if (v0 + p >= 130) break;
#pragma unroll
            for (int ip = 0; ip < 8; ip++) {
                float2 f = up2(acc[p][ip]);
                yb[(2 * ip) * 16900 + p] = f.x;
                yb[(2 * ip + 1) * 16900 + p] = f.y;
            }
        }
    }
}

// ---- Z0: out0 = -convt(Y0,W00,s1,p2) - convt(Y1,W10,s2,p3,op1) + diag + bias --
__global__ __launch_bounds__(256, 2) void k_z0(const float* __restrict__ x0,
                                               const float* __restrict__ W00,
                                               const float* __restrict__ W10,
                                               const float* __restrict__ b0,
                                               float* __restrict__ out,
                                               int bbase) {
    extern __shared__ u64 sm[];
    u64* sW = sm; u64* sBk = sm + 1152; u64* sT = sm + 1664;
    int t = threadIdx.x;
    for (int idx = t; idx < 1152; idx += 256) {
        int ip = idx & 7, rest = idx >> 3, tap = rest % 9, o = rest / 9;
        float wa = -__ldg(W00 + (o * 16 + 2 * ip) * 9 + tap);
        float wb = -__ldg(W00 + (o * 16 + 2 * ip + 1) * 9 + tap);
        sW[idx] = pk2(wa, wb);
    }
    for (int idx = t; idx < 512; idx += 256) {
        int ip = idx & 7, n = (idx >> 3) & 15, rc = idx >> 7;
        float a0 = d_blk0[(rc * 16 + 2 * ip) * 16 + n];
        float a1 = d_blk0[(rc * 16 + 2 * ip + 1) * 16 + n];
        sBk[idx] = pk2(a0, a1);
    }
    for (int idx = t; idx < 2304; idx += 256) {
        int ip = idx & 7, rest = idx >> 3, o = rest & 31, tap = rest >> 5;
        float wa = -__ldg(W10 + (o * 16 + 2 * ip) * 9 + tap);
        float wb = -__ldg(W10 + (o * 16 + 2 * ip + 1) * 9 + tap);
        sT[idx] = pk2(wa, wb);
    }
    __syncthreads();
    int b = bbase + blockIdx.z, lane = t & 31, warp = t >> 5;
    int h = blockIdx.y * 8 + warp;
    int w0 = (blockIdx.x * 32 + lane) * 4;
    u64 acc[4][8];
#pragma unroll
    for (int p = 0; p < 4; p++)
#pragma unroll
        for (int ip = 0; ip < 8; ip++) acc[p][ip] = 0ull;

    const float* yb = d_Y0 + (long)b * 1065024 + h * 258 + w0;
#pragma unroll 1
    for (int o = 0; o < 16; o++) {
        const float* yc = yb + o * 66564;
        float yv[3][6];
#pragma unroll
        for (int rr = 0; rr < 3; rr++) {
            float2 a = *reinterpret_cast<const float2*>(yc + rr * 258);
            float2 c = *reinterpret_cast<const float2*>(yc + rr * 258 + 2);
            float2 e = *reinterpret_cast<const float2*>(yc + rr * 258 + 4);
            yv[rr][0] = a.x; yv[rr][1] = a.y; yv[rr][2] = c.x;
            yv[rr][3] = c.y; yv[rr][4] = e.x; yv[rr][5] = e.y;
        }
        const u64* wbase = sW + o * 72;
#pragma unroll
        for (int dy = 0; dy < 3; dy++)
#pragma unroll
            for (int dx = 0; dx < 3; dx++) {
                const u64* wp = wbase + (dy * 3 + dx) * 8;
                u64 wr[8];
#pragma unroll
                for (int ip = 0; ip < 8; ip++) wr[ip] = wp[ip];
#pragma unroll
                for (int p = 0; p < 4; p++) {
                    u64 a = dup2(yv[2 - dy][p + 2 - dx]);
#pragma unroll
                    for (int ip = 0; ip < 8; ip++) dfma(acc[p][ip], wr[ip], a);
                }
            }
    }
    {
        int qc = (w0 >> 1) + 1;
        int hp = h & 1;
        int ntap = hp ? 2 : 1;
        int dy0 = hp ? 0 : 1;
        int qr0 = hp ? ((h + 3) >> 1) : ((h >> 1) + 1);
        int qr1 = (h + 1) >> 1;
        const float* y1b = d_Y1 + (long)b * 540800;
#pragma unroll 1
        for (int o = 0; o < 32; o++) {
            const float* yo = y1b + o * 16900;
            for (int tt = 0; tt < ntap; tt++) {
                int dy = tt ? 2 : dy0;
                int qr = tt ? qr1 : qr0;
                const float* yr = yo + qr * 130 + qc;
                float yA = __ldg(yr), yB = __ldg(yr + 1), yC = __ldg(yr + 2);
                u64 aA = dup2(yA), aB = dup2(yB), aC = dup2(yC);
                const u64* w0p = sT + ((dy * 3 + 0) * 32 + o) * 8;
                const u64* w1p = sT + ((dy * 3 + 1) * 32 + o) * 8;
                const u64* w2p = sT + ((dy * 3 + 2) * 32 + o) * 8;
#pragma unroll
                for (int ip = 0; ip < 8; ip++) {
                    u64 r0v = w0p[ip], r1v = w1p[ip], r2v = w2p[ip];
                    dfma(acc[0][ip], r1v, aA);
                    dfma(acc[1][ip], r0v, aB);
                    dfma(acc[1][ip], r2v, aA);
                    dfma(acc[2][ip], r1v, aB);
                    dfma(acc[3][ip], r0v, aC);
                    dfma(acc[3][ip], r2v, aB);
                }
            }
        }
    }
    {
        int r = h & 1;
        const u64* sb0 = sBk + (r * 2 + 0) * 128;
        const u64* sb1 = sBk + (r * 2 + 1) * 128;
        const float* xq = x0 + (long)b * 1048576 + h * 256 + w0;
#pragma unroll 1
        for (int n = 0; n < 16; n++) {
            float4 xv = *reinterpret_cast<const float4*>(xq + n * 65536);
            u64 a0 = dup2(xv.x), a1 = dup2(xv.y), a2 = dup2(xv.z), a3 = dup2(xv.w);
            const u64* b0p = sb0 + n * 8;
            const u64* b1p = sb1 + n * 8;
#pragma unroll
            for (int ip = 0; ip < 8; ip++) {
                u64 e = b0p[ip], od = b1p[ip];
                dfma(acc[0][ip], e, a0);
                dfma(acc[1][ip], od, a1);
                dfma(acc[2][ip], e, a2);
                dfma(acc[3][ip], od, a3);
            }
        }
    }
    float bs = d_bscale[0];
    const float* bb = b0 + h * 256 + w0;
    float* ob = out + (long)b * 1048576 + h * 256 + w0;
#pragma unroll
    for (int ip = 0; ip < 8; ip++) {
        float2 f0 = up2(acc[0][ip]), f1 = up2(acc[1][ip]), f2 = up2(acc[2][ip]), f3 = up2(acc[3][ip]);
        float4 bv0 = *reinterpret_cast<const float4*>(bb + (2 * ip) * 65536);
        float4 bv1 = *reinterpret_cast<const float4*>(bb + (2 * ip + 1) * 65536);
        *(float4*)(ob + (2 * ip) * 65536) =
            make_float4(fmaf(bs, bv0.x, f0.x), fmaf(bs, bv0.y, f1.x),
                        fmaf(bs, bv0.z, f2.x), fmaf(bs, bv0.w, f3.x));
        *(float4*)(ob + (2 * ip + 1) * 65536) =
            make_float4(fmaf(bs, bv1.x, f0.y), fmaf(bs, bv1.y, f1.y),
                        fmaf(bs, bv1.z, f2.y), fmaf(bs, bv1.w, f3.y));
    }
}

// -------- Z1: out1 = -convt(Y1,W11,s1,p2) + diag(blk1,x1) + bias ---------------
__global__ __launch_bounds__(256, 2) void k_z1(const float* __restrict__ x1,
                                               const float* __restrict__ W11,
                                               const float* __restrict__ b1,
                                               float* __restrict__ out1,
                                               int bbase) {
    extern __shared__ u64 sm[];
    u64* sW = sm; u64* sB = sm + 2304;
    int t = threadIdx.x;
    int half = blockIdx.z & 1, b = bbase + (blockIdx.z >> 1);
    for (int idx = t; idx < 2304; idx += 256) {
        int ip = idx & 7, rest = idx >> 3, tap = rest % 9, o = rest / 9;
        float wa = -__ldg(W11 + (o * 32 + half * 16 + 2 * ip) * 9 + tap);
        float wb = -__ldg(W11 + (o * 32 + half * 16 + 2 * ip + 1) * 9 + tap);
        sW[idx] = pk2(wa, wb);
    }
    for (int idx = t; idx < 128; idx += 256) {
        int ip = idx & 7, n = idx >> 3;
        float a0 = d_blk1[half * 256 + (2 * ip) * 16 + n];
        float a1 = d_blk1[half * 256 + (2 * ip + 1) * 16 + n];
        sB[idx] = pk2(a0, a1);
    }
    __syncthreads();
    int lane = t & 31, warp = t >> 5;
    int h = blockIdx.y * 8 + warp;
    int w0 = lane * 4;
    u64 acc[4][8];
#pragma unroll
    for (int p = 0; p < 4; p++)
#pragma unroll
        for (int ip = 0; ip < 8; ip++) acc[p][ip] = 0ull;
    const float* yb = d_Y1 + (long)b * 540800 + h * 130 + w0;
#pragma unroll 1
    for (int o = 0; o < 32; o++) {
        const float* yc = yb + o * 16900;
        float yv[3][6];
#pragma unroll
        for (int rr = 0; rr < 3; rr++) {
            float2 a = *reinterpret_cast<const float2*>(yc + rr * 130);
            float2 c = *reinterpret_cast<const float2*>(yc + rr * 130 + 2);
            float2 e = *reinterpret_cast<const float2*>(yc + rr * 130 + 4);
            yv[rr][0] = a.x; yv[rr][1] = a.y; yv[rr][2] = c.x;
            yv[rr][3] = c.y; yv[rr][4] = e.x; yv[rr][5] = e.y;
        }
        const u64* wbase = sW + o * 72;
#pragma unroll
        for (int dy = 0; dy < 3; dy++)
#pragma unroll
            for (int dx = 0; dx < 3; dx++) {
                const u64* wp = wbase + (dy * 3 + dx) * 8;
                u64 wr[8];
#pragma unroll
                for (int ip = 0; ip < 8; ip++) wr[ip] = wp[ip];
#pragma unroll
                for (int p = 0; p < 4; p++) {
                    u64 a = dup2(yv[2 - dy][p + 2 - dx]);
#pragma unroll
                    for (int ip = 0; ip < 8; ip++) dfma(acc[p][ip], wr[ip], a);
                }
            }
    }
    {
        const float* xq = x1 + (long)b * 524288 + (long)(half * 16) * 16384 + h * 128 + w0;
#pragma unroll 1
        for (int n = 0; n < 16; n++) {
            float4 xv = *reinterpret_cast<const float4*>(xq + n * 16384);
            u64 a0 = dup2(xv.x), a1 = dup2(xv.y), a2 = dup2(xv.z), a3 = dup2(xv.w);
            const u64* bp = sB + n * 8;
#pragma unroll
            for (int ip = 0; ip < 8; ip++) {
                u64 e = bp[ip];
                dfma(acc[0][ip], e, a0);
                dfma(acc[1][ip], e, a1);
                dfma(acc[2][ip], e, a2);
                dfma(acc[3][ip], e, a3);
            }
        }
    }
    float bs = d_bscale[1];
    const float* bb = b1 + (long)(half * 16) * 16384 + h * 128 + w0;
    float* ob = out1 + (long)b * 524288 + (long)(half * 16) * 16384 + h * 128 + w0;
#pragma unroll
    for (int ip = 0; ip < 8; ip++) {
        float2 f0 = up2(acc[0][ip]), f1 = up2(acc[1][ip]), f2 = up2(acc[2][ip]), f3 = up2(acc[3][ip]);
        float4 bv0 = *reinterpret_cast<const float4*>(bb + (2 * ip) * 16384);
        float4 bv1 = *reinterpret_cast<const float4*>(bb + (2 * ip + 1) * 16384);
        *(float4*)(ob + (2 * ip) * 16384) =
            make_float4(fmaf(bs, bv0.x, f0.x), fmaf(bs, bv0.y, f1.x),
                        fmaf(bs, bv0.z, f2.x), fmaf(bs, bv0.w, f3.x));
        *(float4*)(ob + (2 * ip + 1) * 16384) =
            make_float4(fmaf(bs, bv1.x, f0.y), fmaf(bs, bv1.y, f1.y),
                        fmaf(bs, bv1.z, f2.y), fmaf(bs, bv1.w, f3.y));
    }
}

// ---------------- launch: two batch pipelines + prep branch ----------------
extern "C" void kernel_launch(void* const* d_in, const int* in_sizes, int n_in,
                              void* d_out, int out_size) {
    const float* x0  = (const float*)d_in[0];
    const float* x1  = (const float*)d_in[1];
    const float* W00 = (const float*)d_in[2];
    const float* W10 = (const float*)d_in[3];
    const float* W11 = (const float*)d_in[4];
    const float* b0  = (const float*)d_in[5];
    const float* b1  = (const float*)d_in[6];
    const float* g   = (const float*)d_in[7];
    float* out0 = (float*)d_out;
    float* out1 = out0 + (long)16 * 16 * 256 * 256;

    static cudaStream_t sPrep = nullptr, sP1 = nullptr;
    static cudaEvent_t eFork = nullptr, ePrep = nullptr, eP1 = nullptr;
    if (sPrep == nullptr) {
        cudaStreamCreateWithFlags(&sPrep, cudaStreamNonBlocking);
        cudaStreamCreateWithFlags(&sP1, cudaStreamNonBlocking);
        cudaEventCreateWithFlags(&eFork, cudaEventDisableTiming);
        cudaEventCreateWithFlags(&ePrep, cudaEventDisableTiming);
        cudaEventCreateWithFlags(&eP1, cudaEventDisableTiming);
    }

    cudaEventRecord(eFork, 0);
    cudaStreamWaitEvent(sPrep, eFork, 0);
    cudaStreamWaitEvent(sP1, eFork, 0);

    // prep branch
    k_ssq<<<192, 256, 0, sPrep>>>(b0, b1);
    k_prep<<<6, 256, 0, sPrep>>>(W00, W10, W11, g);
    cudaEventRecord(ePrep, sPrep);

    // pipeline 0 (origin stream): batches 0..7
    k_y1<<<dim3(17, 1, 16), 256, 3456 * 8>>>(x0, x1, W10, W11, 0);
    k_y0<<<dim3(66, 1, 8), 256, 1152 * 8>>>(x0, W00, 0);
    cudaStreamWaitEvent(0, ePrep, 0);
    k_z1<<<dim3(1, 16, 16), 256, 2432 * 8>>>(x1, W11, b1, out1, 0);
    k_z0<<<dim3(2, 32, 8), 256, 3968 * 8>>>(x0, W00, W10, b0, out0, 0);

    // pipeline 1 (sP1): batches 8..15
    k_y1<<<dim3(17, 1, 16), 256, 3456 * 8, sP1>>>(x0, x1, W10, W11, 8);
    k_y0<<<dim3(66, 1, 8), 256, 1152 * 8, sP1>>>(x0, W00, 8);
    cudaStreamWaitEvent(sP1, ePrep, 0);
    k_z1<<<dim3(1, 16, 16), 256, 2432 * 8, sP1>>>(x1, W11, b1, out1, 8);
    k_z0<<<dim3(2, 32, 8), 256, 3968 * 8, sP1>>>(x0, W00, W10, b0, out0, 8);
    cudaEventRecord(eP1, sP1);

    // join
    cudaStreamWaitEvent(0, eP1, 0);
}

// round 16
// speedup vs baseline: 1.2375x; 1.0066x over previous
#include <cuda_runtime.h>

// ---------------- scratch ----------------
__device__ __align__(16) float d_Y0[16 * 16 * 258 * 258];   // (B,16,258,258)
__device__ __align__(16) float d_Y1[16 * 32 * 130 * 130];   // (B,32,130,130)
__device__ float d_blk0[1024];   // [r2][c2][m16][n16]
__device__ float d_blk1[512];    // [g2][m16][n16]
__device__ float d_part[192];
__device__ float d_bscale[2];

typedef unsigned long long u64;

// ---------------- f32x2 helpers ----------------
__device__ __forceinline__ u64 pk2(float a, float b) {
    u64 r;
    asm("mov.b64 %0, {%1, %2};" : "=l"(r) : "r"(__float_as_uint(a)), "r"(__float_as_uint(b)));
    return r;
}
__device__ __forceinline__ u64 dup2(float a) { return pk2(a, a); }
__device__ __forceinline__ void dfma(u64& d, u64 a, u64 b) {
    asm("fma.rn.f32x2 %0, %1, %2, %0;" : "+l"(d) : "l"(a), "l"(b));
}
__device__ __forceinline__ float2 up2(u64 v) {
    unsigned lo, hi;
    asm("mov.b64 {%0, %1}, %2;" : "=r"(lo), "=r"(hi) : "l"(v));
    return make_float2(__uint_as_float(lo), __uint_as_float(hi));
}
__device__ __forceinline__ void ldw8(const u64* p, u64 wr[8]) {
    const ulonglong2* q = (const ulonglong2*)p;
    ulonglong2 a = q[0], b = q[1], c = q[2], d = q[3];
    wr[0] = a.x; wr[1] = a.y; wr[2] = b.x; wr[3] = b.y;
    wr[4] = c.x; wr[5] = c.y; wr[6] = d.x; wr[7] = d.y;
}

// ---------------- P1: partial sum of squares for b0,b1 ----------------
__global__ __launch_bounds__(256) void k_ssq(const float* __restrict__ b0,
                                             const float* __restrict__ b1) {
    __shared__ float red[256];
    int bid = blockIdx.x, t = threadIdx.x;
    const float* src; long base;
    if (bid < 128) { src = b0; base = (long)bid * 8192; }
    else           { src = b1; base = (long)(bid - 128) * 8192; }
    float s = 0.f;
#pragma unroll
    for (int k = 0; k < 32; k++) { float v = __ldg(src + base + k * 256 + t); s += v * v; }
    red[t] = s; __syncthreads();
    for (int off = 128; off; off >>= 1) { if (t < off) red[t] += red[t + off]; __syncthreads(); }
    if (t == 0) d_part[bid] = red[0];
}

// ---------------- P2 (parallel, 6 blocks): bscale + Gram matrices --------------
__global__ __launch_bounds__(256) void k_prep(const float* __restrict__ W00,
                                              const float* __restrict__ W10,
                                              const float* __restrict__ W11,
                                              const float* __restrict__ g) {
    __shared__ float sw[9216];
    int blk = blockIdx.x, t = threadIdx.x;
    if (blk == 0 && t == 0) {
        float s0 = 0.f, s1 = 0.f;
        for (int i = 0; i < 128; i++) s0 += d_part[i];
        for (int i = 128; i < 192; i++) s1 += d_part[i];
        d_bscale[0] = __ldg(g) * rsqrtf(s0);
        d_bscale[1] = __ldg(g + 1) * rsqrtf(s1);
    }
    if (blk < 4) {
        for (int i = t; i < 2304; i += 256) sw[i] = __ldg(W00 + i);
        for (int i = t; i < 4608; i += 256) sw[2304 + i] = __ldg(W10 + i);
        __syncthreads();
        const float* s0 = sw;
        const float* s1 = sw + 2304;
        int e = blk * 256 + t;
        int n = e & 15, m = (e >> 4) & 15, c = (e >> 8) & 1, r = (e >> 9) & 1;
        float acc = 0.f;
        for (int o = 0; o < 16; o++) {
            const float* pm = s0 + (o * 16 + m) * 9;
            const float* pn = s0 + (o * 16 + n) * 9;
#pragma unroll
            for (int ij = 0; ij < 9; ij++) acc += pm[ij] * pn[ij];
        }
#pragma unroll
        for (int i1 = 0; i1 < 3; i1++) {
            if (((i1 + 1) & 1) != r) continue;
#pragma unroll
            for (int j1 = 0; j1 < 3; j1++) {
                if (((j1 + 1) & 1) != c) continue;
                int ij = i1 * 3 + j1;
                for (int o = 0; o < 32; o++)
                    acc += s1[(o * 16 + m) * 9 + ij] * s1[(o * 16 + n) * 9 + ij];
            }
        }
        d_blk0[e] = acc;
    } else {
        for (int i = t; i < 9216; i += 256) sw[i] = __ldg(W11 + i);
        __syncthreads();
        int e = (blk - 4) * 256 + t;
        int n = e & 15, m = (e >> 4) & 15, gg = e >> 8;
        float acc = 0.f;
        for (int o = 0; o < 32; o++) {
            const float* pm = sw + (o * 32 + gg * 16 + m) * 9;
            const float* pn = sw + (o * 32 + gg * 16 + n) * 9;
#pragma unroll
            for (int ij = 0; ij < 9; ij++) acc += pm[ij] * pn[ij];
        }
        d_blk1[e] = acc;
    }
}

// ---------------- Y0 = conv(x0, W00, s1, p2); dy-outer + ic prefetch ----------
__global__ __launch_bounds__(256, 2) void k_y0(const float* __restrict__ x0,
                                               const float* __restrict__ W00,
                                               int bbase) {
    extern __shared__ u64 sm[];
    int t = threadIdx.x;
    for (int idx = t; idx < 1152; idx += 256) {
        int ip = idx & 7, rest = idx >> 3, tap = rest % 9, ic = rest / 9;
        float wa = __ldg(W00 + ((2 * ip) * 16 + ic) * 9 + tap);
        float wb = __ldg(W00 + ((2 * ip + 1) * 16 + ic) * 9 + tap);
        sm[idx] = pk2(wa, wb);
    }
    __syncthreads();
    int b = bbase + blockIdx.z;
    int item = blockIdx.x * 256 + t;
    int r = item / 65, q = item - r * 65;
    int w0 = q * 4;
    bool valid = (r < 258);
    u64 acc[4][8];
#pragma unroll
    for (int p = 0; p < 4; p++)
#pragma unroll
        for (int ip = 0; ip < 8; ip++) acc[p][ip] = 0ull;
    const float* xb = x0 + (long)b * 1048576;
#pragma unroll 1
    for (int dy = 0; dy < 3; dy++) {
        int iy = r - 2 + dy;
        bool rowok = valid && iy >= 0 && iy < 256;
        const float* rowp = xb + iy * 256;
        float v[6];
#pragma unroll
        for (int j = 0; j < 6; j++) {
            int ix = w0 - 2 + j;
            v[j] = (rowok && ix >= 0 && ix < 256) ? __ldg(rowp + ix) : 0.f;
        }
#pragma unroll 1
        for (int ic = 0; ic < 16; ic++) {
            int icn = ic < 15 ? ic + 1 : ic;
            const float* nrow = xb + icn * 65536 + iy * 256;
            float nv[6];
#pragma unroll
            for (int j = 0; j < 6; j++) {
                int ix = w0 - 2 + j;
                nv[j] = (rowok && ix >= 0 && ix < 256) ? __ldg(nrow + ix) : 0.f;
            }
            const u64* wbase = sm + ic * 72 + dy * 24;
#pragma unroll
            for (int dx = 0; dx < 3; dx++) {
                u64 wr[8];
                ldw8(wbase + dx * 8, wr);
#pragma unroll
                for (int p = 0; p < 4; p++) {
                    u64 a = dup2(v[p + dx]);
#pragma unroll
                    for (int ip = 0; ip < 8; ip++) dfma(acc[p][ip], wr[ip], a);
                }
            }
#pragma unroll
            for (int j = 0; j < 6; j++) v[j] = nv[j];
        }
    }
    if (valid) {
        float* yb = d_Y0 + (long)b * 1065024 + r * 258 + w0;
        if (w0 + 4 <= 258) {
#pragma unroll
            for (int ip = 0; ip < 8; ip++) {
                float2 f0 = up2(acc[0][ip]), f1 = up2(acc[1][ip]), f2 = up2(acc[2][ip]), f3 = up2(acc[3][ip]);
                yb[(2 * ip) * 66564 + 0] = f0.x; yb[(2 * ip) * 66564 + 1] = f1.x;
                yb[(2 * ip) * 66564 + 2] = f2.x; yb[(2 * ip) * 66564 + 3] = f3.x;
                yb[(2 * ip + 1) * 66564 + 0] = f0.y; yb[(2 * ip + 1) * 66564 + 1] = f1.y;
                yb[(2 * ip + 1) * 66564 + 2] = f2.y; yb[(2 * ip + 1) * 66564 + 3] = f3.y;
            }
        } else {
#pragma unroll
            for (int p = 0; p < 4; p++) {
                if (w0 + p >= 258) break;
#pragma unroll
                for (int ip = 0; ip < 8; ip++) {
                    float2 f = up2(acc[p][ip]);
                    yb[(2 * ip) * 66564 + p] = f.x;
                    yb[(2 * ip + 1) * 66564 + p] = f.y;
                }
            }
        }
    }
}

// ------- Y1 = conv(x0,W10,s2,p3) + conv(x1,W11,s1,p2); ic prefetch ------------
__global__ __launch_bounds__(256, 2) void k_y1(const float* __restrict__ x0,
                                               const float* __restrict__ x1,
                                               const float* __restrict__ W10,
                                               const float* __restrict__ W11,
                                               int bbase) {
    extern __shared__ u64 sm[];
    u64* sA = sm; u64* sB2 = sm + 1152;
    int t = threadIdx.x;
    int half = blockIdx.z & 1, b = bbase + (blockIdx.z >> 1);
    for (int idx = t; idx < 1152; idx += 256) {
        int ip = idx & 7, rest = idx >> 3, tap = rest % 9, ic = rest / 9;
        float wa = __ldg(W10 + ((half * 16 + 2 * ip) * 16 + ic) * 9 + tap);
        float wb = __ldg(W10 + ((half * 16 + 2 * ip + 1) * 16 + ic) * 9 + tap);
        sA[idx] = pk2(wa, wb);
    }
    for (int idx = t; idx < 2304; idx += 256) {
        int ip = idx & 7, rest = idx >> 3, tap = rest % 9, ic = rest / 9;
        float wa = __ldg(W11 + ((half * 16 + 2 * ip) * 32 + ic) * 9 + tap);
        float wb = __ldg(W11 + ((half * 16 + 2 * ip + 1) * 32 + ic) * 9 + tap);
        sB2[idx] = pk2(wa, wb);
    }
    __syncthreads();
    int item = blockIdx.x * 256 + t;
    int u = item / 33, q = item - u * 33;
    int v0 = q * 4;
    bool valid = (u < 130);
    u64 acc[4][8];
#pragma unroll
    for (int p = 0; p < 4; p++)
#pragma unroll
        for (int ip = 0; ip < 8; ip++) acc[p][ip] = 0ull;
    const float* xa = x0 + (long)b * 1048576;
#pragma unroll 1
    for (int dy = 0; dy < 3; dy++) {
        int iy = 2 * u - 3 + dy;
        bool rowok = valid && iy >= 0 && iy < 256;
        const float* rowp = xa + iy * 256;
        float v[9];
#pragma unroll
        for (int j = 0; j < 9; j++) {
            int ix = 2 * v0 - 3 + j;
            v[j] = (rowok && ix >= 0 && ix < 256) ? __ldg(rowp + ix) : 0.f;
        }
#pragma unroll 1
        for (int ic = 0; ic < 16; ic++) {
            int icn = ic < 15 ? ic + 1 : ic;
            const float* nrow = xa + icn * 65536 + iy * 256;
            float nv[9];
#pragma unroll
            for (int j = 0; j < 9; j++) {
                int ix = 2 * v0 - 3 + j;
                nv[j] = (rowok && ix >= 0 && ix < 256) ? __ldg(nrow + ix) : 0.f;
            }
            const u64* wbase = sA + ic * 72 + dy * 24;
#pragma unroll
            for (int dx = 0; dx < 3; dx++) {
                u64 wr[8];
                ldw8(wbase + dx * 8, wr);
#pragma unroll
                for (int p = 0; p < 4; p++) {
                    u64 a = dup2(v[2 * p + dx]);
#pragma unroll
                    for (int ip = 0; ip < 8; ip++) dfma(acc[p][ip], wr[ip], a);
                }
            }
#pragma unroll
            for (int j = 0; j < 9; j++) v[j] = nv[j];
        }
    }
    const float* xb1 = x1 + (long)b * 524288;
#pragma unroll 1
    for (int dy = 0; dy < 3; dy++) {
        int iy = u - 2 + dy;
        bool rowok = valid && iy >= 0 && iy < 128;
        const float* rowp = xb1 + iy * 128;
        float v[6];
#pragma unroll
        for (int j = 0; j < 6; j++) {
            int ix = v0 - 2 + j;
            v[j] = (rowok && ix >= 0 && ix < 128) ? __ldg(rowp + ix) : 0.f;
        }
#pragma unroll 1
        for (int ic = 0; ic < 32; ic++) {
            int icn = ic < 31 ? ic + 1 : ic;
            const float* nrow = xb1 + icn * 16384 + iy * 128;
            float nv[6];
#pragma unroll
            for (int j = 0; j < 6; j++) {
                int ix = v0 - 2 + j;
                nv[j] = (rowok && ix >= 0 && ix < 128) ? __ldg(nrow + ix) : 0.f;
            }
            const u64* wbase = sB2 + ic * 72 + dy * 24;
#pragma unroll
            for (int dx = 0; dx < 3; dx++) {
                u64 wr[8];
                ldw8(wbase + dx * 8, wr);
#pragma unroll
                for (int p = 0; p < 4; p++) {
                    u64 a = dup2(v[p + dx]);
#pragma unroll
                    for (int ip = 0; ip < 8; ip++) dfma(acc[p][ip], wr[ip], a);
                }
            }
#pragma unroll
            for (int j = 0; j < 6; j++) v[j] = nv[j];
        }
    }
    if (valid) {
        float* yb = d_Y1 + (long)b * 540800 + (long)(half * 16) * 16900 + u * 130 + v0;
#pragma unroll
        for (int p = 0; p < 4; p++) {
            if (v0 + p >= 130) break;
#pragma unroll
            for (int ip = 0; ip < 8; ip++) {
                float2 f = up2(acc[p][ip]);
                yb[(2 * ip) * 16900 + p] = f.x;
                yb[(2 * ip + 1) * 16900 + p] = f.y;
            }
        }
    }
}

// ---- Z0: out0 = -convt(Y0,W00,s1,p2) - convt(Y1,W10,s2,p3,op1) + diag + bias --
__global__ __launch_bounds__(256, 2) void k_z0(const float* __restrict__ x0,
                                               const float* __restrict__ W00,
                                               const float* __restrict__ W10,
                                               const float* __restrict__ b0,
                                               float* __restrict__ out,
                                               int bbase) {
    extern __shared__ u64 sm[];
    u64* sW = sm; u64* sBk = sm + 1152; u64* sT = sm + 1664;
    int t = threadIdx.x;
    for (int idx = t; idx < 1152; idx += 256) {
        int ip = idx & 7, rest = idx >> 3, tap = rest % 9, o = rest / 9;
        float wa = -__ldg(W00 + (o * 16 + 2 * ip) * 9 + tap);
        float wb = -__ldg(W00 + (o * 16 + 2 * ip + 1) * 9 + tap);
        sW[idx] = pk2(wa, wb);
    }
    for (int idx = t; idx < 512; idx += 256) {
        int ip = idx & 7, n = (idx >> 3) & 15, rc = idx >> 7;
        float a0 = d_blk0[(rc * 16 + 2 * ip) * 16 + n];
        float a1 = d_blk0[(rc * 16 + 2 * ip + 1) * 16 + n];
        sBk[idx] = pk2(a0, a1);
    }
    for (int idx = t; idx < 2304; idx += 256) {
        int ip = idx & 7, rest = idx >> 3, o = rest & 31, tap = rest >> 5;
        float wa = -__ldg(W10 + (o * 16 + 2 * ip) * 9 + tap);
        float wb = -__ldg(W10 + (o * 16 + 2 * ip + 1) * 9 + tap);
        sT[idx] = pk2(wa, wb);
    }
    __syncthreads();
    int b = bbase + blockIdx.z, lane = t & 31, warp = t >> 5;
    int h = blockIdx.y * 8 + warp;
    int w0 = (blockIdx.x * 32 + lane) * 4;
    u64 acc[4][8];
#pragma unroll
    for (int p = 0; p < 4; p++)
#pragma unroll
        for (int ip = 0; ip < 8; ip++) acc[p][ip] = 0ull;

    const float* yb = d_Y0 + (long)b * 1065024 + h * 258 + w0;
#pragma unroll 1
    for (int o = 0; o < 16; o++) {
        const float* yc = yb + o * 66564;
        float yv[3][6];
#pragma unroll
        for (int rr = 0; rr < 3; rr++) {
            float2 a = *reinterpret_cast<const float2*>(yc + rr * 258);
            float2 c = *reinterpret_cast<const float2*>(yc + rr * 258 + 2);
            float2 e = *reinterpret_cast<const float2*>(yc + rr * 258 + 4);
            yv[rr][0] = a.x; yv[rr][1] = a.y; yv[rr][2] = c.x;
            yv[rr][3] = c.y; yv[rr][4] = e.x; yv[rr][5] = e.y;
        }
        const u64* wbase = sW + o * 72;
#pragma unroll
        for (int dy = 0; dy < 3; dy++)
#pragma unroll
            for (int dx = 0; dx < 3; dx++) {
                const u64* wp = wbase + (dy * 3 + dx) * 8;
                u64 wr[8];
#pragma unroll
                for (int ip = 0; ip < 8; ip++) wr[ip] = wp[ip];
#pragma unroll
                for (int p = 0; p < 4; p++) {
                    u64 a = dup2(yv[2 - dy][p + 2 - dx]);
#pragma unroll
                    for (int ip = 0; ip < 8; ip++) dfma(acc[p][ip], wr[ip], a);
                }
            }
    }
    {
        int qc = (w0 >> 1) + 1;
        int hp = h & 1;
        int ntap = hp ? 2 : 1;
        int dy0 = hp ? 0 : 1;
        int qr0 = hp ? ((h + 3) >> 1) : ((h >> 1) + 1);
        int qr1 = (h + 1) >> 1;
        const float* y1b = d_Y1 + (long)b * 540800;
#pragma unroll 1
        for (int o = 0; o < 32; o++) {
            const float* yo = y1b + o * 16900;
            for (int tt = 0; tt < ntap; tt++) {
                int dy = tt ? 2 : dy0;
                int qr = tt ? qr1 : qr0;
                const float* yr = yo + qr * 130 + qc;
                float yA = __ldg(yr), yB = __ldg(yr + 1), yC = __ldg(yr + 2);
                u64 aA = dup2(yA), aB = dup2(yB), aC = dup2(yC);
                const u64* w0p = sT + ((dy * 3 + 0) * 32 + o) * 8;
                const u64* w1p = sT + ((dy * 3 + 1) * 32 + o) * 8;
                const u64* w2p = sT + ((dy * 3 + 2) * 32 + o) * 8;
#pragma unroll
                for (int ip = 0; ip < 8; ip++) {
                    u64 r0v = w0p[ip], r1v = w1p[ip], r2v = w2p[ip];
                    dfma(acc[0][ip], r1v, aA);
                    dfma(acc[1][ip], r0v, aB);
                    dfma(acc[1][ip], r2v, aA);
                    dfma(acc[2][ip], r1v, aB);
                    dfma(acc[3][ip], r0v, aC);
                    dfma(acc[3][ip], r2v, aB);
                }
            }
        }
    }
    {
        int r = h & 1;
        const u64* sb0 = sBk + (r * 2 + 0) * 128;
        const u64* sb1 = sBk + (r * 2 + 1) * 128;
        const float* xq = x0 + (long)b * 1048576 + h * 256 + w0;
#pragma unroll 1
        for (int n = 0; n < 16; n++) {
            float4 xv = *reinterpret_cast<const float4*>(xq + n * 65536);
            u64 a0 = dup2(xv.x), a1 = dup2(xv.y), a2 = dup2(xv.z), a3 = dup2(xv.w);
            const u64* b0p = sb0 + n * 8;
            const u64* b1p = sb1 + n * 8;
#pragma unroll
            for (int ip = 0; ip < 8; ip++) {
                u64 e = b0p[ip], od = b1p[ip];
                dfma(acc[0][ip], e, a0);
                dfma(acc[1][ip], od, a1);
                dfma(acc[2][ip], e, a2);
                dfma(acc[3][ip], od, a3);
            }
        }
    }
    float bs = d_bscale[0];
    const float* bb = b0 + h * 256 + w0;
    float* ob = out + (long)b * 1048576 + h * 256 + w0;
#pragma unroll
    for (int ip = 0; ip < 8; ip++) {
        float2 f0 = up2(acc[0][ip]), f1 = up2(acc[1][ip]), f2 = up2(acc[2][ip]), f3 = up2(acc[3][ip]);
        float4 bv0 = *reinterpret_cast<const float4*>(bb + (2 * ip) * 65536);
        float4 bv1 = *reinterpret_cast<const float4*>(bb + (2 * ip + 1) * 65536);
        *(float4*)(ob + (2 * ip) * 65536) =
            make_float4(fmaf(bs, bv0.x, f0.x), fmaf(bs, bv0.y, f1.x),
                        fmaf(bs, bv0.z, f2.x), fmaf(bs, bv0.w, f3.x));
        *(float4*)(ob + (2 * ip + 1) * 65536) =
            make_float4(fmaf(bs, bv1.x, f0.y), fmaf(bs, bv1.y, f1.y),
                        fmaf(bs, bv1.z, f2.y), fmaf(bs, bv1.w, f3.y));
    }
}

// -------- Z1: out1 = -convt(Y1,W11,s1,p2) + diag(blk1,x1) + bias ---------------
__global__ __launch_bounds__(256, 2) void k_z1(const float* __restrict__ x1,
                                               const float* __restrict__ W11,
                                               const float* __restrict__ b1,
                                               float* __restrict__ out1,
                                               int bbase) {
    extern __shared__ u64 sm[];
    u64* sW = sm; u64* sB = sm + 2304;
    int t = threadIdx.x;
    int half = blockIdx.z & 1, b = bbase + (blockIdx.z >> 1);
    for (int idx = t; idx < 2304; idx += 256) {
        int ip = idx & 7, rest = idx >> 3, tap = rest % 9, o = rest / 9;
        float wa = -__ldg(W11 + (o * 32 + half * 16 + 2 * ip) * 9 + tap);
        float wb = -__ldg(W11 + (o * 32 + half * 16 + 2 * ip + 1) * 9 + tap);
        sW[idx] = pk2(wa, wb);
    }
    for (int idx = t; idx < 128; idx += 256) {
        int ip = idx & 7, n = idx >> 3;
        float a0 = d_blk1[half * 256 + (2 * ip) * 16 + n];
        float a1 = d_blk1[half * 256 + (2 * ip + 1) * 16 + n];
        sB[idx] = pk2(a0, a1);
    }
    __syncthreads();
    int lane = t & 31, warp = t >> 5;
    int h = blockIdx.y * 8 + warp;
    int w0 = lane * 4;
    u64 acc[4][8];
#pragma unroll
    for (int p = 0; p < 4; p++)
#pragma unroll
        for (int ip = 0; ip < 8; ip++) acc[p][ip] = 0ull;
    const float* yb = d_Y1 + (long)b * 540800 + h * 130 + w0;
#pragma unroll 1
    for (int o = 0; o < 32; o++) {
        const float* yc = yb + o * 16900;
        float yv[3][6];
#pragma unroll
        for (int rr = 0; rr < 3; rr++) {
            float2 a = *reinterpret_cast<const float2*>(yc + rr * 130);
            float2 c = *reinterpret_cast<const float2*>(yc + rr * 130 + 2);
            float2 e = *reinterpret_cast<const float2*>(yc + rr * 130 + 4);
            yv[rr][0] = a.x; yv[rr][1] = a.y; yv[rr][2] = c.x;
            yv[rr][3] = c.y; yv[rr][4] = e.x; yv[rr][5] = e.y;
        }
        const u64* wbase = sW + o * 72;
#pragma unroll
        for (int dy = 0; dy < 3; dy++)
#pragma unroll
            for (int dx = 0; dx < 3; dx++) {
                const u64* wp = wbase + (dy * 3 + dx) * 8;
                u64 wr[8];
#pragma unroll
                for (int ip = 0; ip < 8; ip++) wr[ip] = wp[ip];
#pragma unroll
                for (int p = 0; p < 4; p++) {
                    u64 a = dup2(yv[2 - dy][p + 2 - dx]);
#pragma unroll
                    for (int ip = 0; ip < 8; ip++) dfma(acc[p][ip], wr[ip], a);
                }
            }
    }
    {
        const float* xq = x1 + (long)b * 524288 + (long)(half * 16) * 16384 + h * 128 + w0;
#pragma unroll 1
        for (int n = 0; n < 16; n++) {
            float4 xv = *reinterpret_cast<const float4*>(xq + n * 16384);
            u64 a0 = dup2(xv.x), a1 = dup2(xv.y), a2 = dup2(xv.z), a3 = dup2(xv.w);
            const u64* bp = sB + n * 8;
#pragma unroll
            for (int ip = 0; ip < 8; ip++) {
                u64 e = bp[ip];
                dfma(acc[0][ip], e, a0);
                dfma(acc[1][ip], e, a1);
                dfma(acc[2][ip], e, a2);
                dfma(acc[3][ip], e, a3);
            }
        }
    }
    float bs = d_bscale[1];
    const float* bb = b1 + (long)(half * 16) * 16384 + h * 128 + w0;
    float* ob = out1 + (long)b * 524288 + (long)(half * 16) * 16384 + h * 128 + w0;
#pragma unroll
    for (int ip = 0; ip < 8; ip++) {
        float2 f0 = up2(acc[0][ip]), f1 = up2(acc[1][ip]), f2 = up2(acc[2][ip]), f3 = up2(acc[3][ip]);
        float4 bv0 = *reinterpret_cast<const float4*>(bb + (2 * ip) * 16384);
        float4 bv1 = *reinterpret_cast<const float4*>(bb + (2 * ip + 1) * 16384);
        *(float4*)(ob + (2 * ip) * 16384) =
            make_float4(fmaf(bs, bv0.x, f0.x), fmaf(bs, bv0.y, f1.x),
                        fmaf(bs, bv0.z, f2.x), fmaf(bs, bv0.w, f3.x));
        *(float4*)(ob + (2 * ip + 1) * 16384) =
            make_float4(fmaf(bs, bv1.x, f0.y), fmaf(bs, bv1.y, f1.y),
                        fmaf(bs, bv1.z, f2.y), fmaf(bs, bv1.w, f3.y));
    }
}

// ------- launch: two STAGGERED batch pipelines + prep branch (2 extra streams) --
extern "C" void kernel_launch(void* const* d_in, const int* in_sizes, int n_in,
                              void* d_out, int out_size) {
    const float* x0  = (const float*)d_in[0];
    const float* x1  = (const float*)d_in[1];
    const float* W00 = (const float*)d_in[2];
    const float* W10 = (const float*)d_in[3];
    const float* W11 = (const float*)d_in[4];
    const float* b0  = (const float*)d_in[5];
    const float* b1  = (const float*)d_in[6];
    const float* g   = (const float*)d_in[7];
    float* out0 = (float*)d_out;
    float* out1 = out0 + (long)16 * 16 * 256 * 256;

    static cudaStream_t sPrep = nullptr, sP1 = nullptr;
    static cudaEvent_t eFork = nullptr, ePrep = nullptr, eP1 = nullptr;
    if (sPrep == nullptr) {
        cudaStreamCreateWithFlags(&sPrep, cudaStreamNonBlocking);
        cudaStreamCreateWithFlags(&sP1, cudaStreamNonBlocking);
        cudaEventCreateWithFlags(&eFork, cudaEventDisableTiming);
        cudaEventCreateWithFlags(&ePrep, cudaEventDisableTiming);
        cudaEventCreateWithFlags(&eP1, cudaEventDisableTiming);
    }

    cudaEventRecord(eFork, 0);
    cudaStreamWaitEvent(sPrep, eFork, 0);
    cudaStreamWaitEvent(sP1, eFork, 0);

    // prep branch
    k_ssq<<<192, 256, 0, sPrep>>>(b0, b1);
    k_prep<<<6, 256, 0, sPrep>>>(W00, W10, W11, g);
    cudaEventRecord(ePrep, sPrep);

    // pipeline A (origin stream): batches 0..7, order y1, y0, z1, z0
    k_y1<<<dim3(17, 1, 16), 256, 3456 * 8>>>(x0, x1, W10, W11, 0);
    k_y0<<<dim3(66, 1, 8), 256, 1152 * 8>>>(x0, W00, 0);
    cudaStreamWaitEvent(0, ePrep, 0);
    k_z1<<<dim3(1, 16, 16), 256, 2432 * 8>>>(x1, W11, b1, out1, 0);
    k_z0<<<dim3(2, 32, 8), 256, 3968 * 8>>>(x0, W00, W10, b0, out0, 0);

    // pipeline B (sP1): batches 8..15, REVERSED order y0, y1, z0, z1
    k_y0<<<dim3(66, 1, 8), 256, 1152 * 8, sP1>>>(x0, W00, 8);
    k_y1<<<dim3(17, 1, 16), 256, 3456 * 8, sP1>>>(x0, x1, W10, W11, 8);
    cudaStreamWaitEvent(sP1, ePrep, 0);
    k_z0<<<dim3(2, 32, 8), 256, 3968 * 8, sP1>>>(x0, W00, W10, b0, out0, 8);
    k_z1<<<dim3(1, 16, 16), 256, 2432 * 8, sP1>>>(x1, W11, b1, out1, 8);
    cudaEventRecord(eP1, sP1);

    // join
    cudaStreamWaitEvent(0, eP1, 0);
}